// round 1
// baseline (speedup 1.0000x reference)
#include <cuda_runtime.h>

#define B_    8
#define N_    1024
#define T_    8
#define CIN   64
#define CO    64
#define COLS  512          // T_ * CO
#define NB    (B_ * N_)    // 8192

// ---------------- scratch (static device arrays; no allocation) ----------------
static __device__ __align__(16) float g_rowsum[NB];
static __device__ __align__(16) float g_cf[NB * T_];        // [b][n][t] exp(-ptd - tsq/2)
static __device__ __align__(16) float g_u [NB * T_];        // [b][n][t] exp(+ptd)
static __device__ __align__(16) float g_kB[CIN * COLS];     // [c][t*64+o]
static __device__ __align__(16) float g_H [NB * COLS];      // [b][m][t*64+o]
static __device__ __align__(16) float g_preT[T_][NB * CO];  // per-t partial of pre
static __device__ __align__(16) float g_pre[NB * CO];
static __device__ __align__(16) float g_part [64 * CO];
static __device__ __align__(16) float g_part2[64 * CO];
static __device__ __align__(16) float g_scale[CO];
static __device__ __align__(16) float g_bias [CO];

// ---------------- f32x2 helpers (FFMA2 only reachable via PTX) ----------------
__device__ __forceinline__ unsigned long long pk2(float lo, float hi) {
    unsigned long long r;
    asm("mov.b64 %0, {%1, %2};" : "=l"(r) : "f"(lo), "f"(hi));
    return r;
}
__device__ __forceinline__ void fma2(unsigned long long& c,
                                     unsigned long long a,
                                     unsigned long long b) {
    asm("fma.rn.f32x2 %0, %1, %2, %0;" : "+l"(c) : "l"(a), "l"(b));
}
__device__ __forceinline__ float lo32(unsigned long long v) {
    return __uint_as_float((unsigned)(v & 0xFFFFFFFFull));
}
__device__ __forceinline__ float hi32(unsigned long long v) {
    return __uint_as_float((unsigned)(v >> 32));
}

// ---------------- K0a: transpose k_tensor [o][c][t] -> kB [c][t*64+o] ----------
__global__ void k_transpose(const float* __restrict__ kt) {
    for (int i = threadIdx.x; i < CIN * COLS; i += blockDim.x) {
        int c = i >> 9;
        int t = (i >> 6) & 7;
        int o = i & 63;
        g_kB[i] = kt[(o * CIN + c) * T_ + t];
    }
}

// ---------------- K0b: rowsum, cf, u ----------------
__global__ __launch_bounds__(256) void k_prep(const float* __restrict__ pts,
                                              const float* __restrict__ trans) {
    __shared__ float px[N_], py[N_], pz[N_], psq[N_];
    __shared__ float ttx[T_], tty[T_], ttz[T_], ttq[T_];
    __shared__ float red[256];

    int b  = blockIdx.x >> 3;
    int n0 = (blockIdx.x & 7) * 128;
    int tid = threadIdx.x;

    for (int n = tid; n < N_; n += 256) {
        const float* pp = pts + (b * N_ + n) * 3;
        float x = pp[0], y = pp[1], z = pp[2];
        px[n] = x; py[n] = y; pz[n] = z;
        psq[n] = x * x + y * y + z * z;
    }
    if (tid < T_) {
        const float* tp = trans + (b * T_ + tid) * 3;
        float x = tp[0], y = tp[1], z = tp[2];
        ttx[tid] = x; tty[tid] = y; ttz[tid] = z;
        ttq[tid] = x * x + y * y + z * z;
    }
    __syncthreads();

    int row  = tid & 127;
    int half = tid >> 7;
    int n = n0 + row;
    float xn = px[n], yn = py[n], zn = pz[n], sn = psq[n];

    float s = 0.0f;
    int m0 = half * 512;
    for (int m = m0; m < m0 + 512; ++m) {
        float d = sn + psq[m] - 2.0f * (xn * px[m] + yn * py[m] + zn * pz[m]);
        s += __expf(-0.5f * d);
    }
    red[tid] = s;
    __syncthreads();
    if (half == 0) {
        float tot = s + red[row + 128];
        g_rowsum[b * N_ + n] = tot;
        #pragma unroll
        for (int t = 0; t < T_; ++t) {
            float ptd = xn * ttx[t] + yn * tty[t] + zn * ttz[t];
            g_cf[(b * N_ + n) * T_ + t] = __expf(-ptd - 0.5f * ttq[t]);
            g_u [(b * N_ + n) * T_ + t] = __expf(ptd);
        }
    }
}

// ---------------- K1: H = ((functions/rowsum) @ kB) * cf ----------------
// block: (b, m-tile 128, col-chunk 128). dyn smem: w_s[128][64] + kBs[64][128] = 64KB
__global__ __launch_bounds__(256) void k_H(const float* __restrict__ func) {
    extern __shared__ float sm[];
    float* w_s = sm;                 // [128][64]
    float* kBs = sm + 128 * 64;      // [64][128]
    __shared__ float rinv[128];

    int bx = blockIdx.x;
    int b  = bx >> 5;
    int mt = (bx >> 2) & 7;
    int ct = bx & 3;
    int m0 = mt * 128, c0 = ct * 128;
    int tid = threadIdx.x;

    if (tid < 128) rinv[tid] = 1.0f / g_rowsum[b * N_ + m0 + tid];
    __syncthreads();

    for (int i = tid; i < 128 * 16; i += 256) {   // float4 count
        int m = i >> 4, c4 = i & 15;
        float4 v = *(const float4*)(func + (b * N_ + m0 + m) * CIN + c4 * 4);
        float r = rinv[m];
        v.x *= r; v.y *= r; v.z *= r; v.w *= r;
        *(float4*)(w_s + m * 64 + c4 * 4) = v;
    }
    for (int i = tid; i < 64 * 32; i += 256) {    // float4 count
        int c = i >> 5, j = i & 31;
        *(float4*)(kBs + c * 128 + j * 4) = *(const float4*)(g_kB + c * COLS + c0 + j * 4);
    }
    __syncthreads();

    int ty = tid >> 4, tx = tid & 15;
    unsigned long long acc[8][4];
    #pragma unroll
    for (int i = 0; i < 8; ++i)
        #pragma unroll
        for (int j = 0; j < 4; ++j) acc[i][j] = 0ULL;

    #pragma unroll 8
    for (int c = 0; c < CIN; ++c) {
        float4 b0 = *(const float4*)(kBs + c * 128 + tx * 8);
        float4 b1 = *(const float4*)(kBs + c * 128 + tx * 8 + 4);
        unsigned long long bp0 = pk2(b0.x, b0.y), bp1 = pk2(b0.z, b0.w);
        unsigned long long bp2 = pk2(b1.x, b1.y), bp3 = pk2(b1.z, b1.w);
        #pragma unroll
        for (int i = 0; i < 8; ++i) {
            float a = w_s[(ty * 8 + i) * 64 + c];
            unsigned long long a2 = pk2(a, a);
            fma2(acc[i][0], a2, bp0);
            fma2(acc[i][1], a2, bp1);
            fma2(acc[i][2], a2, bp2);
            fma2(acc[i][3], a2, bp3);
        }
    }

    int t = (c0 + tx * 8) >> 6;   // constant per thread
    #pragma unroll
    for (int i = 0; i < 8; ++i) {
        int m = m0 + ty * 8 + i;
        float cfv = g_cf[(b * N_ + m) * T_ + t];
        float4 o0, o1;
        o0.x = lo32(acc[i][0]) * cfv; o0.y = hi32(acc[i][0]) * cfv;
        o0.z = lo32(acc[i][1]) * cfv; o0.w = hi32(acc[i][1]) * cfv;
        o1.x = lo32(acc[i][2]) * cfv; o1.y = hi32(acc[i][2]) * cfv;
        o1.z = lo32(acc[i][3]) * cfv; o1.w = hi32(acc[i][3]) * cfv;
        float* dst = g_H + (b * N_ + m) * COLS + c0 + tx * 8;
        *(float4*)(dst)     = o0;
        *(float4*)(dst + 4) = o1;
    }
}

// ---------------- K2: main GEMM  preT[t] = u * (E @ H) ----------------
// block: (b, n-tile 128, col-chunk 128). dyn smem 80KB:
//   p stage 16KB + As[2][32][128] 32KB + Bs[2][32][128] 32KB
__global__ __launch_bounds__(256, 2) void k_main(const float* __restrict__ pts) {
    extern __shared__ float sm[];
    float* px  = sm;
    float* py  = sm + 1024;
    float* pz  = sm + 2048;
    float* psq = sm + 3072;
    float* As  = sm + 4096;          // [2][32][128]
    float* Bs  = sm + 4096 + 8192;   // [2][32][128]

    int bx = blockIdx.x;
    int b  = bx >> 5;
    int nt = (bx >> 2) & 7;
    int ct = bx & 3;
    int n0 = nt * 128, c0 = ct * 128;
    int tid = threadIdx.x;

    const float* Hb = g_H + b * N_ * COLS;

    // prefetch H tile 0 into regs (independent of smem staging)
    float4 pf[4];
    #pragma unroll
    for (int p = 0; p < 4; ++p) {
        int lin = tid + p * 256;
        int kk = lin >> 5, j = lin & 31;
        pf[p] = *(const float4*)(Hb + kk * COLS + c0 + j * 4);
    }

    // stage all batch points + norms
    for (int n = tid; n < N_; n += 256) {
        const float* pp = pts + (b * N_ + n) * 3;
        float x = pp[0], y = pp[1], z = pp[2];
        px[n] = x; py[n] = y; pz[n] = z;
        psq[n] = x * x + y * y + z * z;
    }
    __syncthreads();

    int row    = tid & 127;  // constant n-row this thread generates E for
    int kkbase = tid >> 7;
    float xn = px[n0 + row], yn = py[n0 + row], zn = pz[n0 + row], sn = psq[n0 + row];

    // generate E tile 0 + commit H tile 0
    {
        #pragma unroll
        for (int j = 0; j < 16; ++j) {
            int kk = kkbase + 2 * j;
            int m = kk;
            float d = sn + psq[m] - 2.0f * (xn * px[m] + yn * py[m] + zn * pz[m]);
            As[kk * 128 + row] = __expf(-0.5f * d);
        }
        #pragma unroll
        for (int p = 0; p < 4; ++p) {
            int lin = tid + p * 256;
            int kk = lin >> 5, j = lin & 31;
            *(float4*)(Bs + kk * 128 + j * 4) = pf[p];
        }
    }
    __syncthreads();

    unsigned long long acc[8][4];
    #pragma unroll
    for (int i = 0; i < 8; ++i)
        #pragma unroll
        for (int j = 0; j < 4; ++j) acc[i][j] = 0ULL;

    int ty = tid >> 4, tx = tid & 15;

    for (int it = 0; it < 32; ++it) {
        int cur = it & 1, nxt = cur ^ 1;
        if (it < 31) {
            int k0 = (it + 1) * 32;
            #pragma unroll
            for (int p = 0; p < 4; ++p) {
                int lin = tid + p * 256;
                int kk = lin >> 5, j = lin & 31;
                pf[p] = *(const float4*)(Hb + (k0 + kk) * COLS + c0 + j * 4);
            }
        }
        const float* Ac = As + cur * 4096 + ty * 8;
        const float* Bc = Bs + cur * 4096 + tx * 8;
        #pragma unroll 8
        for (int kk = 0; kk < 32; ++kk) {
            float4 a0 = *(const float4*)(Ac + kk * 128);
            float4 a1 = *(const float4*)(Ac + kk * 128 + 4);
            float4 b0 = *(const float4*)(Bc + kk * 128);
            float4 b1 = *(const float4*)(Bc + kk * 128 + 4);
            unsigned long long bp0 = pk2(b0.x, b0.y), bp1 = pk2(b0.z, b0.w);
            unsigned long long bp2 = pk2(b1.x, b1.y), bp3 = pk2(b1.z, b1.w);
            float af[8] = {a0.x, a0.y, a0.z, a0.w, a1.x, a1.y, a1.z, a1.w};
            #pragma unroll
            for (int i = 0; i < 8; ++i) {
                unsigned long long a2 = pk2(af[i], af[i]);
                fma2(acc[i][0], a2, bp0);
                fma2(acc[i][1], a2, bp1);
                fma2(acc[i][2], a2, bp2);
                fma2(acc[i][3], a2, bp3);
            }
        }
        if (it < 31) {
            int k0 = (it + 1) * 32;
            float* An = As + nxt * 4096;
            #pragma unroll
            for (int j = 0; j < 16; ++j) {
                int kk = kkbase + 2 * j;
                int m = k0 + kk;
                float d = sn + psq[m] - 2.0f * (xn * px[m] + yn * py[m] + zn * pz[m]);
                An[kk * 128 + row] = __expf(-0.5f * d);
            }
            float* Bn = Bs + nxt * 4096;
            #pragma unroll
            for (int p = 0; p < 4; ++p) {
                int lin = tid + p * 256;
                int kk = lin >> 5, j = lin & 31;
                *(float4*)(Bn + kk * 128 + j * 4) = pf[p];
            }
        }
        __syncthreads();
    }

    // epilogue: fold u_t[n], write per-t plane (no atomics, fully deterministic)
    int t = (c0 >> 6) + (tx >> 3);
    int obase = (tx & 7) * 8;
    float* dst = g_preT[t];
    #pragma unroll
    for (int i = 0; i < 8; ++i) {
        int n = n0 + ty * 8 + i;
        float uv = g_u[(b * N_ + n) * T_ + t];
        float4 o0, o1;
        o0.x = lo32(acc[i][0]) * uv; o0.y = hi32(acc[i][0]) * uv;
        o0.z = lo32(acc[i][1]) * uv; o0.w = hi32(acc[i][1]) * uv;
        o1.x = lo32(acc[i][2]) * uv; o1.y = hi32(acc[i][2]) * uv;
        o1.z = lo32(acc[i][3]) * uv; o1.w = hi32(acc[i][3]) * uv;
        float* d0 = dst + (b * N_ + n) * CO + obase;
        *(float4*)(d0)     = o0;
        *(float4*)(d0 + 4) = o1;
    }
}

// ---------------- K3: sum over t planes + BN partial stats ----------------
__global__ __launch_bounds__(256) void k_stats() {
    __shared__ float sh[256], sh2[256];
    int blk = blockIdx.x;       // 64 blocks, 128 rows each
    int o  = threadIdx.x & 63;
    int rg = threadIdx.x >> 6;
    int r0 = blk * 128;

    float s = 0.0f, s2 = 0.0f;
    for (int r = r0 + rg; r < r0 + 128; r += 4) {
        float p = 0.0f;
        #pragma unroll
        for (int t = 0; t < T_; ++t) p += g_preT[t][r * CO + o];
        g_pre[r * CO + o] = p;
        s += p; s2 += p * p;
    }
    sh[threadIdx.x] = s; sh2[threadIdx.x] = s2;
    __syncthreads();
    if (rg == 0) {
        float ts  = s  + sh [o + 64] + sh [o + 128] + sh [o + 192];
        float ts2 = s2 + sh2[o + 64] + sh2[o + 128] + sh2[o + 192];
        g_part [blk * 64 + o] = ts;
        g_part2[blk * 64 + o] = ts2;
    }
}

// ---------------- K4: finalize BN scale/bias ----------------
__global__ void k_finalize(const float* __restrict__ gamma,
                           const float* __restrict__ beta) {
    int o = threadIdx.x;
    float s = 0.0f, s2 = 0.0f;
    for (int i = 0; i < 64; ++i) { s += g_part[i * 64 + o]; s2 += g_part2[i * 64 + o]; }
    float inv = 1.0f / (float)NB;
    float mean = s * inv;
    float var = s2 * inv - mean * mean;
    float sc = gamma[o] * rsqrtf(var + 1e-5f);
    g_scale[o] = sc;
    g_bias[o]  = beta[o] - mean * sc;
}

// ---------------- K5: apply BN + ReLU ----------------
__global__ __launch_bounds__(256) void k_apply(float* __restrict__ out) {
    int idx = blockIdx.x * 256 + threadIdx.x;   // 131072 float4s
    int e0 = idx * 4;
    int o0 = e0 & 63;
    float4 p = *(const float4*)(g_pre + e0);
    float4 r;
    r.x = fmaxf(fmaf(p.x, g_scale[o0 + 0], g_bias[o0 + 0]), 0.0f);
    r.y = fmaxf(fmaf(p.y, g_scale[o0 + 1], g_bias[o0 + 1]), 0.0f);
    r.z = fmaxf(fmaf(p.z, g_scale[o0 + 2], g_bias[o0 + 2]), 0.0f);
    r.w = fmaxf(fmaf(p.w, g_scale[o0 + 3], g_bias[o0 + 3]), 0.0f);
    *(float4*)(out + e0) = r;
}

// ---------------- launch ----------------
extern "C" void kernel_launch(void* const* d_in, const int* in_sizes, int n_in,
                              void* d_out, int out_size) {
    (void)in_sizes; (void)n_in; (void)out_size;
    const float* pts   = (const float*)d_in[0];
    const float* trans = (const float*)d_in[1];
    const float* func  = (const float*)d_in[2];
    const float* kt    = (const float*)d_in[3];
    const float* gamma = (const float*)d_in[4];
    const float* beta  = (const float*)d_in[5];
    float* out = (float*)d_out;

    cudaFuncSetAttribute(k_main, cudaFuncAttributeMaxDynamicSharedMemorySize, 81920);
    cudaFuncSetAttribute(k_H,    cudaFuncAttributeMaxDynamicSharedMemorySize, 65536);

    k_transpose<<<1, 256>>>(kt);
    k_prep<<<64, 256>>>(pts, trans);
    k_H<<<256, 256, 65536>>>(func);
    k_main<<<256, 256, 81920>>>(pts);
    k_stats<<<64, 256>>>();
    k_finalize<<<1, 64>>>(gamma, beta);
    k_apply<<<512, 256>>>(out);
}

// round 3
// speedup vs baseline: 2.2130x; 2.2130x over previous
#include <cuda_runtime.h>
#include <cstdint>

#define B_    8
#define N_    1024
#define T_    8
#define CIN   64
#define CO    64
#define COLS  512          // T_ * CO
#define NB    (B_ * N_)    // 8192
#define L2E   1.4426950408889634f     // log2(e)
#define NEGH  (-0.72134752044448170f) // -0.5*log2(e)

// ---------------- scratch (static device arrays; no allocation) ----------------
static __device__ __align__(16) float g_rowsum[NB];
static __device__ __align__(16) float g_cf[NB * T_];        // [b][n][t] exp(-ptd - tsq/2)
static __device__ __align__(16) float g_u [NB * T_];        // [b][n][t] exp(+ptd)
static __device__ __align__(16) float g_kB[CIN * COLS];     // [c][t*64+o]
// Ht in B-fragment order: [b][jt(64)][m8(128)][lane(32)][2]  (tf32-rounded)
static __device__ __align__(16) float g_Ht[B_ * 64 * 128 * 32 * 2];
static __device__ __align__(16) float g_preT[T_][NB * CO];  // per-t planes
static __device__ __align__(16) float g_pre[NB * CO];
static __device__ __align__(16) float g_part [64 * CO];
static __device__ __align__(16) float g_part2[64 * CO];
static __device__ __align__(16) float g_scale[CO];
static __device__ __align__(16) float g_bias [CO];

// ---------------- helpers ----------------
__device__ __forceinline__ unsigned long long pk2(float lo, float hi) {
    unsigned long long r;
    asm("mov.b64 %0, {%1, %2};" : "=l"(r) : "f"(lo), "f"(hi));
    return r;
}
__device__ __forceinline__ void fma2(unsigned long long& c,
                                     unsigned long long a,
                                     unsigned long long b) {
    asm("fma.rn.f32x2 %0, %1, %2, %0;" : "+l"(c) : "l"(a), "l"(b));
}
__device__ __forceinline__ float lo32(unsigned long long v) {
    return __uint_as_float((unsigned)(v & 0xFFFFFFFFull));
}
__device__ __forceinline__ float hi32(unsigned long long v) {
    return __uint_as_float((unsigned)(v >> 32));
}
__device__ __forceinline__ float to_tf32(float x) {
    float r;
    asm("cvt.rna.tf32.f32 %0, %1;" : "=f"(r) : "f"(x));
    return r;
}
__device__ __forceinline__ float ex2f(float x) {
    float r;
    asm("ex2.approx.ftz.f32 %0, %1;" : "=f"(r) : "f"(x));
    return r;
}

// mma.sync m16n8k8 tf32 (baseline PTX, works on sm_103 family target)
__device__ __forceinline__ void mma1688(float* c, const uint32_t* a, const uint32_t* b2) {
    asm volatile(
        "mma.sync.aligned.m16n8k8.row.col.f32.tf32.tf32.f32 "
        "{%0,%1,%2,%3}, {%4,%5,%6,%7}, {%8,%9}, {%0,%1,%2,%3};"
        : "+f"(c[0]), "+f"(c[1]), "+f"(c[2]), "+f"(c[3])
        : "r"(a[0]), "r"(a[1]), "r"(a[2]), "r"(a[3]), "r"(b2[0]), "r"(b2[1]));
}

// ---------------- K0a: transpose k_tensor [o][c][t] -> kB [c][t*64+o] ----------
__global__ void k_transpose(const float* __restrict__ kt) {
    int i = blockIdx.x * 256 + threadIdx.x;
    if (i < CIN * COLS) {
        int c = i >> 9;
        int t = (i >> 6) & 7;
        int o = i & 63;
        g_kB[i] = kt[(o * CIN + c) * T_ + t];
    }
}

// ---------------- K0b: rowsum, cf, u ----------------
__global__ __launch_bounds__(256) void k_prep(const float* __restrict__ pts,
                                              const float* __restrict__ trans) {
    __shared__ float px[N_], py[N_], pz[N_], psq[N_];
    __shared__ float ttx[T_], tty[T_], ttz[T_], ttq[T_];
    __shared__ float red[256];

    int b  = blockIdx.x >> 4;
    int n0 = (blockIdx.x & 15) * 64;
    int tid = threadIdx.x;

    for (int n = tid; n < N_; n += 256) {
        const float* pp = pts + (b * N_ + n) * 3;
        float x = pp[0], y = pp[1], z = pp[2];
        px[n] = x; py[n] = y; pz[n] = z;
        psq[n] = x * x + y * y + z * z;
    }
    if (tid < T_) {
        const float* tp = trans + (b * T_ + tid) * 3;
        float x = tp[0], y = tp[1], z = tp[2];
        ttx[tid] = x; tty[tid] = y; ttz[tid] = z;
        ttq[tid] = x * x + y * y + z * z;
    }
    __syncthreads();

    int row  = tid >> 2;
    int part = tid & 3;
    int n = n0 + row;
    float xn = px[n], yn = py[n], zn = pz[n], sn = psq[n];

    float s = 0.0f;
    int m0 = part * 256;
    #pragma unroll 4
    for (int m = m0; m < m0 + 256; ++m) {
        float d = sn + psq[m] - 2.0f * (xn * px[m] + yn * py[m] + zn * pz[m]);
        s += __expf(-0.5f * d);
    }
    red[tid] = s;
    __syncthreads();
    if (part == 0) {
        float tot = s + red[tid + 1] + red[tid + 2] + red[tid + 3];
        g_rowsum[b * N_ + n] = tot;
        #pragma unroll
        for (int t = 0; t < T_; ++t) {
            float ptd = xn * ttx[t] + yn * tty[t] + zn * ttz[t];
            g_cf[(b * N_ + n) * T_ + t] = __expf(-ptd - 0.5f * ttq[t]);
            g_u [(b * N_ + n) * T_ + t] = __expf(ptd);
        }
    }
}

// ---------------- K1: Ht = tf32(((func/rowsum)@kB)*cf) in B-fragment order ----
__global__ __launch_bounds__(256) void k_H(const float* __restrict__ func) {
    extern __shared__ float sm[];
    float* w_s = sm;                 // [128][64]
    float* kBs = sm + 128 * 64;      // [64][128]
    __shared__ float rinv[128];

    int bx = blockIdx.x;
    int b  = bx >> 5;
    int mt = (bx >> 2) & 7;
    int ct = bx & 3;
    int m0 = mt * 128, c0 = ct * 128;
    int tid = threadIdx.x;

    if (tid < 128) rinv[tid] = 1.0f / g_rowsum[b * N_ + m0 + tid];
    __syncthreads();

    for (int i = tid; i < 128 * 16; i += 256) {
        int m = i >> 4, c4 = i & 15;
        float4 v = *(const float4*)(func + (b * N_ + m0 + m) * CIN + c4 * 4);
        float r = rinv[m];
        v.x *= r; v.y *= r; v.z *= r; v.w *= r;
        *(float4*)(w_s + m * 64 + c4 * 4) = v;
    }
    for (int i = tid; i < 64 * 32; i += 256) {
        int c = i >> 5, j = i & 31;
        *(float4*)(kBs + c * 128 + j * 4) = *(const float4*)(g_kB + c * COLS + c0 + j * 4);
    }
    __syncthreads();

    int ty = tid >> 4, tx = tid & 15;
    unsigned long long acc[8][4];
    #pragma unroll
    for (int i = 0; i < 8; ++i)
        #pragma unroll
        for (int j = 0; j < 4; ++j) acc[i][j] = 0ULL;

    #pragma unroll 8
    for (int c = 0; c < CIN; ++c) {
        float4 b0 = *(const float4*)(kBs + c * 128 + tx * 8);
        float4 b1 = *(const float4*)(kBs + c * 128 + tx * 8 + 4);
        unsigned long long bp0 = pk2(b0.x, b0.y), bp1 = pk2(b0.z, b0.w);
        unsigned long long bp2 = pk2(b1.x, b1.y), bp3 = pk2(b1.z, b1.w);
        #pragma unroll
        for (int i = 0; i < 8; ++i) {
            float a = w_s[(ty * 8 + i) * 64 + c];
            unsigned long long a2 = pk2(a, a);
            fma2(acc[i][0], a2, bp0);
            fma2(acc[i][1], a2, bp1);
            fma2(acc[i][2], a2, bp2);
            fma2(acc[i][3], a2, bp3);
        }
    }

    // t is constant across this thread's 8 cols (tx*8 .. tx*8+7 within one 64-block)
    int t = (c0 + tx * 8) >> 6;
    float cf_i[8];
    #pragma unroll
    for (int i = 0; i < 8; ++i)
        cf_i[i] = g_cf[(b * N_ + m0 + ty * 8 + i) * T_ + t];

    // B-fragment layout: addr(float2) = ((b*64 + jt)*128 + m8)*32 + lane
    //   lane = (j&7)*4 + (m&3), elem0 = m&7 in 0..3, elem1 = (m&7)-4 in 4..7
    int jt_g = ct * 16 + tx;           // (c0 + tx*8) >> 3
    int m8   = mt * 16 + ty;           // (m0 + ty*8) >> 3
    float* base = g_Ht + (size_t)(((size_t)(b * 64 + jt_g) * 128 + m8) * 32) * 2;

    #pragma unroll
    for (int jj = 0; jj < 8; ++jj) {
        float v[8];
        #pragma unroll
        for (int i = 0; i < 8; ++i) {
            float raw = (jj & 1) ? hi32(acc[i][jj >> 1]) : lo32(acc[i][jj >> 1]);
            v[i] = to_tf32(raw * cf_i[i]);
        }
        // memory order for lanes jj*4+il: {v0,v4, v1,v5, v2,v6, v3,v7}
        float* dst = base + jj * 8;
        *(float4*)(dst)     = make_float4(v[0], v[4], v[1], v[5]);
        *(float4*)(dst + 4) = make_float4(v[2], v[6], v[3], v[7]);
    }
}

// ---------------- K2: HMMA tf32 GEMM  D = E @ Ht, fold u, write 8 planes ------
// 128 CTAs: b=bx>>4, nt=(bx>>1)&7, ch=bx&1.  CTA tile M128 x N256 x K1024.
// 512 threads = 16 warps, warp grid 4(M) x 4(N), warp tile 32x64.
// dyn smem: pts4 16KB | A[2][4096] 32KB | B[2][8192] 64KB = 114688 B
__global__ __launch_bounds__(512, 1) void k_main(const float* __restrict__ pts) {
    extern __shared__ float sm[];
    float4* pts4 = (float4*)sm;            // [1024] {x,y,z, NEGH*|p|^2}
    float*  Ab   = sm + 4096;              // 2 x 4096 floats (fragment order)
    float*  Bb   = sm + 4096 + 8192;       // 2 x 8192 floats (fragment order)

    int bx = blockIdx.x;
    int b  = bx >> 4;
    int nt = (bx >> 1) & 7;
    int ch = bx & 1;
    int n0 = nt * 128;
    int tid = threadIdx.x;
    int wid = tid >> 5, lane = tid & 31;
    int mw = wid & 3, nw = wid >> 2;

    // stage points
    for (int n = tid; n < N_; n += 512) {
        const float* pp = pts + (b * N_ + n) * 3;
        float x = pp[0], y = pp[1], z = pp[2];
        pts4[n] = make_float4(x, y, z, NEGH * (x * x + y * y + z * z));
    }
    __syncthreads();

    const float4* HtF4 = (const float4*)g_Ht;
    int jt_base = (b * 64 + ch * 32);

    // decode this thread's two A-generation slots (slot = tid, tid+512)
    int laneA[2], mtkA[2], rA[2], cA[2];
    #pragma unroll
    for (int s = 0; s < 2; ++s) {
        int slot = tid + s * 512;
        laneA[s] = slot & 31;
        mtkA[s]  = slot >> 5;                 // mt*4 + k8
        int mt = mtkA[s] >> 2, k8 = mtkA[s] & 3;
        rA[s] = n0 + mt * 16 + (laneA[s] >> 2);
        cA[s] = k8 * 8 + (laneA[s] & 3);
    }

    // B staging decode (4 float4 per thread per chunk)
    int k8S[4], jtS[4], lpS[4];
    #pragma unroll
    for (int p = 0; p < 4; ++p) {
        int idx = p * 512 + tid;
        k8S[p] = idx >> 9;
        jtS[p] = (idx >> 4) & 31;
        lpS[p] = idx & 15;
    }

    float c_[2][8][4];
    #pragma unroll
    for (int i = 0; i < 2; ++i)
        #pragma unroll
        for (int j = 0; j < 8; ++j)
            #pragma unroll
            for (int q = 0; q < 4; ++q) c_[i][j][q] = 0.0f;

    // --- generator for A chunk kc into buffer buf ---
    auto genA = [&](int kc, float* AbN) {
        #pragma unroll
        for (int s = 0; s < 2; ++s) {
            float4 p0 = pts4[rA[s]];
            float4 p1 = pts4[rA[s] + 8];
            int m = kc * 32 + cA[s];
            float4 q0 = pts4[m];
            float4 q1 = pts4[m + 4];
            float d00 = fmaf(p0.z, q0.z, fmaf(p0.y, q0.y, p0.x * q0.x));
            float d10 = fmaf(p1.z, q0.z, fmaf(p1.y, q0.y, p1.x * q0.x));
            float d01 = fmaf(p0.z, q1.z, fmaf(p0.y, q1.y, p0.x * q1.x));
            float d11 = fmaf(p1.z, q1.z, fmaf(p1.y, q1.y, p1.x * q1.x));
            float a0 = to_tf32(ex2f(fmaf(d00, L2E, p0.w + q0.w)));
            float a1 = to_tf32(ex2f(fmaf(d10, L2E, p1.w + q0.w)));
            float a2 = to_tf32(ex2f(fmaf(d01, L2E, p0.w + q1.w)));
            float a3 = to_tf32(ex2f(fmaf(d11, L2E, p1.w + q1.w)));
            *(float4*)(AbN + (mtkA[s] * 32 + laneA[s]) * 4) =
                make_float4(a0, a1, a2, a3);
        }
    };

    // prologue: chunk 0
    float4 pf[4];
    #pragma unroll
    for (int p = 0; p < 4; ++p)
        pf[p] = HtF4[((size_t)(jt_base + jtS[p]) * 128 + 0 * 4 + k8S[p]) * 16 + lpS[p]];
    genA(0, Ab);
    #pragma unroll
    for (int p = 0; p < 4; ++p)
        *(float4*)(Bb + (k8S[p] * 32 + jtS[p]) * 64 + lpS[p] * 4) = pf[p];
    __syncthreads();

    for (int kc = 0; kc < 32; ++kc) {
        int cur = kc & 1, nxt = cur ^ 1;
        if (kc < 31) {
            #pragma unroll
            for (int p = 0; p < 4; ++p)
                pf[p] = HtF4[((size_t)(jt_base + jtS[p]) * 128 + (kc + 1) * 4 + k8S[p]) * 16 + lpS[p]];
        }

        const float* Ac = Ab + cur * 4096;
        const float* Bc = Bb + cur * 8192;
        #pragma unroll
        for (int k8 = 0; k8 < 4; ++k8) {
            uint32_t a[2][4];
            #pragma unroll
            for (int i = 0; i < 2; ++i) {
                uint4 av = *(const uint4*)(Ac + (((mw * 2 + i) * 4 + k8) * 32 + lane) * 4);
                a[i][0] = av.x; a[i][1] = av.y; a[i][2] = av.z; a[i][3] = av.w;
            }
            uint32_t bv[8][2];
            #pragma unroll
            for (int j = 0; j < 8; ++j) {
                uint2 u = *(const uint2*)(Bc + ((k8 * 32 + nw * 8 + j) * 32 + lane) * 2);
                bv[j][0] = u.x; bv[j][1] = u.y;
            }
            #pragma unroll
            for (int i = 0; i < 2; ++i)
                #pragma unroll
                for (int j = 0; j < 8; ++j)
                    mma1688(c_[i][j], a[i], bv[j]);
        }

        if (kc < 31) {
            float* AbN = Ab + nxt * 4096;
            float* BbN = Bb + nxt * 8192;
            genA(kc + 1, AbN);
            #pragma unroll
            for (int p = 0; p < 4; ++p)
                *(float4*)(BbN + (k8S[p] * 32 + jtS[p]) * 64 + lpS[p] * 4) = pf[p];
        }
        __syncthreads();
    }

    // epilogue: fold u_t[n], write plane t (each (t,n,o) written exactly once)
    int t = ch * 4 + nw;
    int colq = (lane & 3) * 2;
    int rbase = n0 + mw * 32 + (lane >> 2);
    #pragma unroll
    for (int i = 0; i < 2; ++i) {
        #pragma unroll
        for (int ro = 0; ro < 2; ++ro) {
            int n = rbase + i * 16 + ro * 8;
            float u = g_u[(b * N_ + n) * T_ + t];
            float* dst = g_preT[t] + (size_t)(b * N_ + n) * CO + colq;
            #pragma unroll
            for (int j = 0; j < 8; ++j) {
                float2 v;
                v.x = c_[i][j][ro * 2 + 0] * u;
                v.y = c_[i][j][ro * 2 + 1] * u;
                *(float2*)(dst + j * 8) = v;
            }
        }
    }
}

// ---------------- K3: sum 8 planes + BN partial stats ----------------
__global__ __launch_bounds__(256) void k_stats() {
    __shared__ float sh[256], sh2[256];
    int blk = blockIdx.x;       // 64 blocks, 128 rows each
    int o  = threadIdx.x & 63;
    int rg = threadIdx.x >> 6;
    int r0 = blk * 128;

    float s = 0.0f, s2 = 0.0f;
    for (int r = r0 + rg; r < r0 + 128; r += 4) {
        float p = 0.0f;
        #pragma unroll
        for (int t = 0; t < T_; ++t) p += g_preT[t][r * CO + o];
        g_pre[r * CO + o] = p;
        s += p; s2 += p * p;
    }
    sh[threadIdx.x] = s; sh2[threadIdx.x] = s2;
    __syncthreads();
    if (rg == 0) {
        float ts  = s  + sh [o + 64] + sh [o + 128] + sh [o + 192];
        float ts2 = s2 + sh2[o + 64] + sh2[o + 128] + sh2[o + 192];
        g_part [blk * 64 + o] = ts;
        g_part2[blk * 64 + o] = ts2;
    }
}

// ---------------- K4: finalize BN scale/bias ----------------
__global__ void k_finalize(const float* __restrict__ gamma,
                           const float* __restrict__ beta) {
    int o = threadIdx.x;
    float s = 0.0f, s2 = 0.0f;
    for (int i = 0; i < 64; ++i) { s += g_part[i * 64 + o]; s2 += g_part2[i * 64 + o]; }
    float inv = 1.0f / (float)NB;
    float mean = s * inv;
    float var = s2 * inv - mean * mean;
    float sc = gamma[o] * rsqrtf(var + 1e-5f);
    g_scale[o] = sc;
    g_bias[o]  = beta[o] - mean * sc;
}

// ---------------- K5: apply BN + ReLU ----------------
__global__ __launch_bounds__(256) void k_apply(float* __restrict__ out) {
    int idx = blockIdx.x * 256 + threadIdx.x;
    int e0 = idx * 4;
    int o0 = e0 & 63;
    float4 p = *(const float4*)(g_pre + e0);
    float4 r;
    r.x = fmaxf(fmaf(p.x, g_scale[o0 + 0], g_bias[o0 + 0]), 0.0f);
    r.y = fmaxf(fmaf(p.y, g_scale[o0 + 1], g_bias[o0 + 1]), 0.0f);
    r.z = fmaxf(fmaf(p.z, g_scale[o0 + 2], g_bias[o0 + 2]), 0.0f);
    r.w = fmaxf(fmaf(p.w, g_scale[o0 + 3], g_bias[o0 + 3]), 0.0f);
    *(float4*)(out + e0) = r;
}

// ---------------- launch ----------------
extern "C" void kernel_launch(void* const* d_in, const int* in_sizes, int n_in,
                              void* d_out, int out_size) {
    (void)in_sizes; (void)n_in; (void)out_size;
    const float* pts   = (const float*)d_in[0];
    const float* trans = (const float*)d_in[1];
    const float* func  = (const float*)d_in[2];
    const float* kt    = (const float*)d_in[3];
    const float* gamma = (const float*)d_in[4];
    const float* beta  = (const float*)d_in[5];
    float* out = (float*)d_out;

    cudaFuncSetAttribute(k_main, cudaFuncAttributeMaxDynamicSharedMemorySize, 114688);
    cudaFuncSetAttribute(k_H,    cudaFuncAttributeMaxDynamicSharedMemorySize, 65536);

    k_transpose<<<128, 256>>>(kt);
    k_prep<<<128, 256>>>(pts, trans);
    k_H<<<256, 256, 65536>>>(func);
    k_main<<<128, 512, 114688>>>(pts);
    k_stats<<<64, 256>>>();
    k_finalize<<<1, 64>>>(gamma, beta);
    k_apply<<<512, 256>>>(out);
}

// round 4
// speedup vs baseline: 2.6463x; 1.1958x over previous
#include <cuda_runtime.h>
#include <cstdint>

#define B_    8
#define N_    1024
#define T_    8
#define CIN   64
#define CO    64
#define COLS  512          // T_ * CO
#define NB    (B_ * N_)    // 8192
#define L2E   1.4426950408889634f     // log2(e)
#define NEGH  (-0.72134752044448170f) // -0.5*log2(e)

// ---------------- scratch (static device arrays; no allocation) ----------------
static __device__ __align__(16) float g_rspart[2][NB];      // rowsum partials (k-halves)
static __device__ __align__(16) float g_cf[NB * T_];        // [b][n][t] exp(-ptd - tsq/2)
static __device__ __align__(16) float g_u [NB * T_];        // [b][n][t] exp(+ptd)
static __device__ __align__(16) float g_kB[CIN * COLS];     // [c][t*64+o]
// E in A-fragment chunk order: [b][nt(8)][kc(32)][slot(1024) float4]
static __device__ __align__(16) float4 g_E4[B_ * 8 * 32 * 1024];
// Ht in B-fragment chunk order: [b][ch(2)][kc(32)][k8(4)][jtl(32)][lane(32)][2]
static __device__ __align__(16) float g_Ht[B_ * 2 * 32 * 4 * 32 * 32 * 2];
static __device__ __align__(16) float g_preT[T_][NB * CO];  // per-t planes
static __device__ __align__(16) float g_pre[NB * CO];
static __device__ __align__(16) float g_part [64 * CO];
static __device__ __align__(16) float g_part2[64 * CO];
static __device__ __align__(16) float g_scale[CO];
static __device__ __align__(16) float g_bias [CO];

// ---------------- helpers ----------------
__device__ __forceinline__ unsigned long long pk2(float lo, float hi) {
    unsigned long long r;
    asm("mov.b64 %0, {%1, %2};" : "=l"(r) : "f"(lo), "f"(hi));
    return r;
}
__device__ __forceinline__ void fma2(unsigned long long& c,
                                     unsigned long long a,
                                     unsigned long long b) {
    asm("fma.rn.f32x2 %0, %1, %2, %0;" : "+l"(c) : "l"(a), "l"(b));
}
__device__ __forceinline__ float lo32(unsigned long long v) {
    return __uint_as_float((unsigned)(v & 0xFFFFFFFFull));
}
__device__ __forceinline__ float hi32(unsigned long long v) {
    return __uint_as_float((unsigned)(v >> 32));
}
__device__ __forceinline__ float to_tf32(float x) {
    float r;
    asm("cvt.rna.tf32.f32 %0, %1;" : "=f"(r) : "f"(x));
    return r;
}
__device__ __forceinline__ float ex2f(float x) {
    float r;
    asm("ex2.approx.ftz.f32 %0, %1;" : "=f"(r) : "f"(x));
    return r;
}
__device__ __forceinline__ uint32_t smem_u32(const void* p) {
    uint32_t a;
    asm("{ .reg .u64 t; cvta.to.shared.u64 t, %1; cvt.u32.u64 %0, t; }" : "=r"(a) : "l"(p));
    return a;
}
__device__ __forceinline__ void cp16(uint32_t s, const void* g) {
    asm volatile("cp.async.cg.shared.global [%0], [%1], 16;" :: "r"(s), "l"(g) : "memory");
}
#define CP_COMMIT() asm volatile("cp.async.commit_group;" ::: "memory")
#define CP_WAIT(n)  asm volatile("cp.async.wait_group %0;" :: "n"(n) : "memory")

// mma.sync m16n8k8 tf32 (baseline PTX)
__device__ __forceinline__ void mma1688(float* c, const uint32_t* a, const uint32_t* b2) {
    asm volatile(
        "mma.sync.aligned.m16n8k8.row.col.f32.tf32.tf32.f32 "
        "{%0,%1,%2,%3}, {%4,%5,%6,%7}, {%8,%9}, {%0,%1,%2,%3};"
        : "+f"(c[0]), "+f"(c[1]), "+f"(c[2]), "+f"(c[3])
        : "r"(a[0]), "r"(a[1]), "r"(a[2]), "r"(a[3]), "r"(b2[0]), "r"(b2[1]));
}

// ---------------- K0a: transpose k_tensor [o][c][t] -> kB [c][t*64+o] ----------
__global__ void k_transpose(const float* __restrict__ kt) {
    int i = blockIdx.x * 256 + threadIdx.x;
    if (i < CIN * COLS) {
        int c = i >> 9;
        int t = (i >> 6) & 7;
        int o = i & 63;
        g_kB[i] = kt[(o * CIN + c) * T_ + t];
    }
}

// ---------------- K0b: generate E (fragment order) + rowsum partials + cf/u ----
// 128 blocks: b = bx>>4, nt = (bx>>1)&7, kh = bx&1 (k-chunks kh*16 .. +15)
__global__ __launch_bounds__(512) void k_prepE(const float* __restrict__ pts,
                                               const float* __restrict__ trans) {
    __shared__ float4 pts4[N_];
    __shared__ float4 tr4[T_];
    __shared__ float red[128 * 17];

    int bx = blockIdx.x;
    int b  = bx >> 4;
    int nt = (bx >> 1) & 7;
    int kh = bx & 1;
    int n0 = nt * 128;
    int tid = threadIdx.x;

    for (int n = tid; n < N_; n += 512) {
        const float* pp = pts + (b * N_ + n) * 3;
        float x = pp[0], y = pp[1], z = pp[2];
        pts4[n] = make_float4(x, y, z, NEGH * (x * x + y * y + z * z));
    }
    if (tid < T_) {
        const float* tp = trans + (b * T_ + tid) * 3;
        float x = tp[0], y = tp[1], z = tp[2];
        tr4[tid] = make_float4(x, y, z, x * x + y * y + z * z);
    }
    __syncthreads();

    int laneA = tid & 31;
    int mtk0  = tid >> 5;           // warp id 0..15
    int mt0   = mtk0 >> 2;
    int k80   = mtk0 & 3;
    int r0    = mt0 * 16 + (laneA >> 2);     // local row 0..63
    int cA0   = k80 * 8 + (laneA & 3);

    float4 pA[2][2];
    pA[0][0] = pts4[n0 + r0];
    pA[0][1] = pts4[n0 + r0 + 8];
    pA[1][0] = pts4[n0 + r0 + 64];
    pA[1][1] = pts4[n0 + r0 + 72];

    float sums[4] = {0.0f, 0.0f, 0.0f, 0.0f};
    size_t ebase = (size_t)(b * 8 + nt) * 32 * 1024;

    for (int kcl = 0; kcl < 16; ++kcl) {
        int kc = kh * 16 + kcl;
        int m = kc * 32 + cA0;
        float4 q0 = pts4[m];
        float4 q1 = pts4[m + 4];
        #pragma unroll
        for (int s = 0; s < 2; ++s) {
            float4 p0 = pA[s][0], p1 = pA[s][1];
            float d00 = fmaf(p0.z, q0.z, fmaf(p0.y, q0.y, p0.x * q0.x));
            float d10 = fmaf(p1.z, q0.z, fmaf(p1.y, q0.y, p1.x * q0.x));
            float d01 = fmaf(p0.z, q1.z, fmaf(p0.y, q1.y, p0.x * q1.x));
            float d11 = fmaf(p1.z, q1.z, fmaf(p1.y, q1.y, p1.x * q1.x));
            float e00 = ex2f(fmaf(d00, L2E, p0.w + q0.w));
            float e10 = ex2f(fmaf(d10, L2E, p1.w + q0.w));
            float e01 = ex2f(fmaf(d01, L2E, p0.w + q1.w));
            float e11 = ex2f(fmaf(d11, L2E, p1.w + q1.w));
            sums[s * 2]     += e00 + e01;
            sums[s * 2 + 1] += e10 + e11;
            g_E4[ebase + (size_t)kc * 1024 + tid + s * 512] =
                make_float4(to_tf32(e00), to_tf32(e10), to_tf32(e01), to_tf32(e11));
        }
    }

    int col = k80 * 4 + (laneA & 3);
    red[(r0     ) * 17 + col] = sums[0];
    red[(r0 +  8) * 17 + col] = sums[1];
    red[(r0 + 64) * 17 + col] = sums[2];
    red[(r0 + 72) * 17 + col] = sums[3];
    __syncthreads();

    if (tid < 128) {
        float rs = 0.0f;
        #pragma unroll
        for (int c = 0; c < 16; ++c) rs += red[tid * 17 + c];
        g_rspart[kh][b * N_ + n0 + tid] = rs;
        if (kh == 0) {
            float4 pn = pts4[n0 + tid];
            #pragma unroll
            for (int t = 0; t < T_; ++t) {
                float4 tv = tr4[t];
                float ptd = fmaf(pn.z, tv.z, fmaf(pn.y, tv.y, pn.x * tv.x));
                g_cf[(b * N_ + n0 + tid) * T_ + t] = __expf(-ptd - 0.5f * tv.w);
                g_u [(b * N_ + n0 + tid) * T_ + t] = __expf(ptd);
            }
        }
    }
}

// ---------------- K1: Ht = tf32(((func/rowsum)@kB)*cf) in B-fragment chunk order
__global__ __launch_bounds__(256) void k_H(const float* __restrict__ func) {
    extern __shared__ float sm[];
    float* w_s = sm;                 // [128][64]
    float* kBs = sm + 128 * 64;      // [64][128]
    __shared__ float rinv[128];

    int bx = blockIdx.x;
    int b  = bx >> 5;
    int mt = (bx >> 2) & 7;
    int ct = bx & 3;
    int m0 = mt * 128, c0 = ct * 128;
    int tid = threadIdx.x;

    if (tid < 128) {
        int idx = b * N_ + m0 + tid;
        rinv[tid] = 1.0f / (g_rspart[0][idx] + g_rspart[1][idx]);
    }
    __syncthreads();

    for (int i = tid; i < 128 * 16; i += 256) {
        int m = i >> 4, c4 = i & 15;
        float4 v = *(const float4*)(func + (b * N_ + m0 + m) * CIN + c4 * 4);
        float r = rinv[m];
        v.x *= r; v.y *= r; v.z *= r; v.w *= r;
        *(float4*)(w_s + m * 64 + c4 * 4) = v;
    }
    for (int i = tid; i < 64 * 32; i += 256) {
        int c = i >> 5, j = i & 31;
        *(float4*)(kBs + c * 128 + j * 4) = *(const float4*)(g_kB + c * COLS + c0 + j * 4);
    }
    __syncthreads();

    int ty = tid >> 4, tx = tid & 15;
    unsigned long long acc[8][4];
    #pragma unroll
    for (int i = 0; i < 8; ++i)
        #pragma unroll
        for (int j = 0; j < 4; ++j) acc[i][j] = 0ULL;

    #pragma unroll 8
    for (int c = 0; c < CIN; ++c) {
        float4 b0 = *(const float4*)(kBs + c * 128 + tx * 8);
        float4 b1 = *(const float4*)(kBs + c * 128 + tx * 8 + 4);
        unsigned long long bp0 = pk2(b0.x, b0.y), bp1 = pk2(b0.z, b0.w);
        unsigned long long bp2 = pk2(b1.x, b1.y), bp3 = pk2(b1.z, b1.w);
        #pragma unroll
        for (int i = 0; i < 8; ++i) {
            float a = w_s[(ty * 8 + i) * 64 + c];
            unsigned long long a2 = pk2(a, a);
            fma2(acc[i][0], a2, bp0);
            fma2(acc[i][1], a2, bp1);
            fma2(acc[i][2], a2, bp2);
            fma2(acc[i][3], a2, bp3);
        }
    }

    int jt_g = ct * 16 + tx;        // global jt 0..63
    int t = jt_g >> 3;
    float cf_i[8];
    #pragma unroll
    for (int i = 0; i < 8; ++i)
        cf_i[i] = g_cf[(b * N_ + m0 + ty * 8 + i) * T_ + t];

    int ch  = jt_g >> 5;
    int jtl = jt_g & 31;
    int m8  = mt * 16 + ty;         // 0..127
    int kc  = m8 >> 2;
    int k8  = m8 & 3;
    float* base = g_Ht +
        (size_t)((((b * 2 + ch) * 32 + kc) * 4 + k8) * 32 + jtl) * 64;

    #pragma unroll
    for (int jj = 0; jj < 8; ++jj) {
        float v[8];
        #pragma unroll
        for (int i = 0; i < 8; ++i) {
            float raw = (jj & 1) ? hi32(acc[i][jj >> 1]) : lo32(acc[i][jj >> 1]);
            v[i] = to_tf32(raw * cf_i[i]);
        }
        float* dst = base + jj * 8;   // lanes jj*4 .. jj*4+3, 2 floats each
        *(float4*)(dst)     = make_float4(v[0], v[4], v[1], v[5]);
        *(float4*)(dst + 4) = make_float4(v[2], v[6], v[3], v[7]);
    }
}

// ---------------- K2: pure cp.async HMMA tf32 GEMM, fold u, write 8 planes ----
// 128 CTAs: b=bx>>4, nt=(bx>>1)&7, ch=bx&1.  M128 x N256 x K1024, 512 threads.
// dyn smem: A 4x16KB + B 4x32KB = 196608 B, 4-stage cp.async pipeline.
__global__ __launch_bounds__(512, 1) void k_main() {
    extern __shared__ float sm[];
    uint32_t sbase = smem_u32(sm);

    int bx = blockIdx.x;
    int b  = bx >> 4;
    int nt = (bx >> 1) & 7;
    int ch = bx & 1;
    int n0 = nt * 128;
    int tid = threadIdx.x;
    int wid = tid >> 5, lane = tid & 31;
    int mw = wid & 3, nw = wid >> 2;

    const float4* EA = g_E4 + (size_t)(b * 8 + nt) * 32 * 1024;
    const float4* HB = (const float4*)g_Ht + (size_t)(b * 2 + ch) * 32 * 2048;
    uint32_t sA = sbase;              // 4 x 16384 B
    uint32_t sB = sbase + 65536;      // 4 x 32768 B

    auto issue = [&](int s) {
        int buf = s & 3;
        uint32_t da = sA + buf * 16384 + tid * 16;
        const float4* ga = EA + (size_t)s * 1024 + tid;
        cp16(da, ga);
        cp16(da + 8192, ga + 512);
        uint32_t db = sB + buf * 32768 + tid * 16;
        const float4* gb = HB + (size_t)s * 2048 + tid;
        #pragma unroll
        for (int p = 0; p < 4; ++p)
            cp16(db + p * 8192, gb + p * 512);
        CP_COMMIT();
    };

    issue(0); issue(1); issue(2);

    float c_[2][8][4];
    #pragma unroll
    for (int i = 0; i < 2; ++i)
        #pragma unroll
        for (int j = 0; j < 8; ++j)
            #pragma unroll
            for (int q = 0; q < 4; ++q) c_[i][j][q] = 0.0f;

    for (int kc = 0; kc < 32; ++kc) {
        if (kc < 30)      { CP_WAIT(2); }
        else if (kc == 30){ CP_WAIT(1); }
        else              { CP_WAIT(0); }
        __syncthreads();

        int buf = kc & 3;
        const float* Ac = sm + buf * 4096;
        const float* Bc = sm + 16384 + buf * 8192;

        #pragma unroll
        for (int k8 = 0; k8 < 4; ++k8) {
            uint32_t a[2][4];
            #pragma unroll
            for (int i = 0; i < 2; ++i) {
                uint4 av = *(const uint4*)(Ac + (((mw * 2 + i) * 4 + k8) * 32 + lane) * 4);
                a[i][0] = av.x; a[i][1] = av.y; a[i][2] = av.z; a[i][3] = av.w;
            }
            uint32_t bv[8][2];
            #pragma unroll
            for (int j = 0; j < 8; ++j) {
                uint2 u = *(const uint2*)(Bc + ((k8 * 32 + nw * 8 + j) * 32 + lane) * 2);
                bv[j][0] = u.x; bv[j][1] = u.y;
            }
            #pragma unroll
            for (int i = 0; i < 2; ++i)
                #pragma unroll
                for (int j = 0; j < 8; ++j)
                    mma1688(c_[i][j], a[i], bv[j]);
        }

        if (kc < 29) issue(kc + 3);
        __syncthreads();
    }

    // epilogue: fold u_t[n], write plane t
    int t = ch * 4 + nw;
    int colq = (lane & 3) * 2;
    int rbase = n0 + mw * 32 + (lane >> 2);
    #pragma unroll
    for (int i = 0; i < 2; ++i) {
        #pragma unroll
        for (int ro = 0; ro < 2; ++ro) {
            int n = rbase + i * 16 + ro * 8;
            float u = g_u[(b * N_ + n) * T_ + t];
            float* dst = g_preT[t] + (size_t)(b * N_ + n) * CO + colq;
            #pragma unroll
            for (int j = 0; j < 8; ++j) {
                float2 v;
                v.x = c_[i][j][ro * 2 + 0] * u;
                v.y = c_[i][j][ro * 2 + 1] * u;
                *(float2*)(dst + j * 8) = v;
            }
        }
    }
}

// ---------------- K3: sum 8 planes + BN partial stats ----------------
__global__ __launch_bounds__(256) void k_stats() {
    __shared__ float sh[256], sh2[256];
    int blk = blockIdx.x;       // 64 blocks, 128 rows each
    int o  = threadIdx.x & 63;
    int rg = threadIdx.x >> 6;
    int r0 = blk * 128;

    float s = 0.0f, s2 = 0.0f;
    for (int r = r0 + rg; r < r0 + 128; r += 4) {
        float p = 0.0f;
        #pragma unroll
        for (int t = 0; t < T_; ++t) p += g_preT[t][r * CO + o];
        g_pre[r * CO + o] = p;
        s += p; s2 += p * p;
    }
    sh[threadIdx.x] = s; sh2[threadIdx.x] = s2;
    __syncthreads();
    if (rg == 0) {
        float ts  = s  + sh [o + 64] + sh [o + 128] + sh [o + 192];
        float ts2 = s2 + sh2[o + 64] + sh2[o + 128] + sh2[o + 192];
        g_part [blk * 64 + o] = ts;
        g_part2[blk * 64 + o] = ts2;
    }
}

// ---------------- K4: finalize BN scale/bias ----------------
__global__ void k_finalize(const float* __restrict__ gamma,
                           const float* __restrict__ beta) {
    int o = threadIdx.x;
    float s = 0.0f, s2 = 0.0f;
    for (int i = 0; i < 64; ++i) { s += g_part[i * 64 + o]; s2 += g_part2[i * 64 + o]; }
    float inv = 1.0f / (float)NB;
    float mean = s * inv;
    float var = s2 * inv - mean * mean;
    float sc = gamma[o] * rsqrtf(var + 1e-5f);
    g_scale[o] = sc;
    g_bias[o]  = beta[o] - mean * sc;
}

// ---------------- K5: apply BN + ReLU ----------------
__global__ __launch_bounds__(256) void k_apply(float* __restrict__ out) {
    int idx = blockIdx.x * 256 + threadIdx.x;
    int e0 = idx * 4;
    int o0 = e0 & 63;
    float4 p = *(const float4*)(g_pre + e0);
    float4 r;
    r.x = fmaxf(fmaf(p.x, g_scale[o0 + 0], g_bias[o0 + 0]), 0.0f);
    r.y = fmaxf(fmaf(p.y, g_scale[o0 + 1], g_bias[o0 + 1]), 0.0f);
    r.z = fmaxf(fmaf(p.z, g_scale[o0 + 2], g_bias[o0 + 2]), 0.0f);
    r.w = fmaxf(fmaf(p.w, g_scale[o0 + 3], g_bias[o0 + 3]), 0.0f);
    *(float4*)(out + e0) = r;
}

// ---------------- launch ----------------
extern "C" void kernel_launch(void* const* d_in, const int* in_sizes, int n_in,
                              void* d_out, int out_size) {
    (void)in_sizes; (void)n_in; (void)out_size;
    const float* pts   = (const float*)d_in[0];
    const float* trans = (const float*)d_in[1];
    const float* func  = (const float*)d_in[2];
    const float* kt    = (const float*)d_in[3];
    const float* gamma = (const float*)d_in[4];
    const float* beta  = (const float*)d_in[5];
    float* out = (float*)d_out;

    cudaFuncSetAttribute(k_main, cudaFuncAttributeMaxDynamicSharedMemorySize, 196608);
    cudaFuncSetAttribute(k_H,    cudaFuncAttributeMaxDynamicSharedMemorySize, 65536);

    k_transpose<<<128, 256>>>(kt);
    k_prepE<<<128, 512>>>(pts, trans);
    k_H<<<256, 256, 65536>>>(func);
    k_main<<<128, 512, 196608>>>();
    k_stats<<<64, 256>>>();
    k_finalize<<<1, 64>>>(gamma, beta);
    k_apply<<<512, 256>>>(out);
}

// round 5
// speedup vs baseline: 2.7469x; 1.0380x over previous
#include <cuda_runtime.h>
#include <cstdint>

#define B_    8
#define N_    1024
#define T_    8
#define CIN   64
#define CO    64
#define COLS  512          // T_ * CO
#define NB    (B_ * N_)    // 8192
#define L2E   1.4426950408889634f     // log2(e)
#define NEGH  (-0.72134752044448170f) // -0.5*log2(e)

// ---------------- scratch (static device arrays; no allocation) ----------------
static __device__ __align__(16) float g_rspart[2][NB];      // rowsum partials (k-halves)
static __device__ __align__(16) float g_cf[NB * T_];        // [b][n][t] exp(-ptd - tsq/2)
static __device__ __align__(16) float g_u [NB * T_];        // [b][n][t] exp(+ptd)
static __device__ __align__(16) float g_kB[CIN * COLS];     // [c][t*64+o]
// E in A-fragment chunk order: [b][nt(8)][kc(32)][mt(8)][k8(4)][lane(32)] float4
static __device__ __align__(16) float4 g_E4[B_ * 8 * 32 * 1024];
// Ht in B-fragment chunk order: [b][ch2(2)][kc(32)][k8(4)][jtl(32)][lane(32)][2]
static __device__ __align__(16) float g_Ht[B_ * 2 * 32 * 4 * 32 * 32 * 2];
static __device__ __align__(16) float g_preT[T_][NB * CO];  // per-t planes
static __device__ __align__(16) float g_pre[NB * CO];
static __device__ __align__(16) float g_part [64 * CO];
static __device__ __align__(16) float g_part2[64 * CO];

// ---------------- helpers ----------------
__device__ __forceinline__ float to_tf32(float x) {
    float r;
    asm("cvt.rna.tf32.f32 %0, %1;" : "=f"(r) : "f"(x));
    return r;
}
__device__ __forceinline__ float ex2f(float x) {
    float r;
    asm("ex2.approx.ftz.f32 %0, %1;" : "=f"(r) : "f"(x));
    return r;
}
__device__ __forceinline__ uint32_t smem_u32(const void* p) {
    uint32_t a;
    asm("{ .reg .u64 t; cvta.to.shared.u64 t, %1; cvt.u32.u64 %0, t; }" : "=r"(a) : "l"(p));
    return a;
}
__device__ __forceinline__ void cp16(uint32_t s, const void* g) {
    asm volatile("cp.async.cg.shared.global [%0], [%1], 16;" :: "r"(s), "l"(g) : "memory");
}
#define CP_COMMIT() asm volatile("cp.async.commit_group;" ::: "memory")
#define CP_WAIT(n)  asm volatile("cp.async.wait_group %0;" :: "n"(n) : "memory")

// mma.sync m16n8k8 tf32 (baseline PTX)
__device__ __forceinline__ void mma1688(float* c, const uint32_t* a, const uint32_t* b2) {
    asm volatile(
        "mma.sync.aligned.m16n8k8.row.col.f32.tf32.tf32.f32 "
        "{%0,%1,%2,%3}, {%4,%5,%6,%7}, {%8,%9}, {%0,%1,%2,%3};"
        : "+f"(c[0]), "+f"(c[1]), "+f"(c[2]), "+f"(c[3])
        : "r"(a[0]), "r"(a[1]), "r"(a[2]), "r"(a[3]), "r"(b2[0]), "r"(b2[1]));
}

// ---------------- K0a: transpose k_tensor [o][c][t] -> kB [c][t*64+o] ----------
__global__ void k_transpose(const float* __restrict__ kt) {
    int i = blockIdx.x * 256 + threadIdx.x;
    if (i < CIN * COLS) {
        int c = i >> 9;
        int t = (i >> 6) & 7;
        int o = i & 63;
        g_kB[i] = kt[(o * CIN + c) * T_ + t];
    }
}

// ---------------- K0b: generate E (fragment order) + rowsum partials + cf/u ----
__global__ __launch_bounds__(512) void k_prepE(const float* __restrict__ pts,
                                               const float* __restrict__ trans) {
    __shared__ float4 pts4[N_];
    __shared__ float4 tr4[T_];
    __shared__ float red[128 * 17];

    int bx = blockIdx.x;
    int b  = bx >> 4;
    int nt = (bx >> 1) & 7;
    int kh = bx & 1;
    int n0 = nt * 128;
    int tid = threadIdx.x;

    for (int n = tid; n < N_; n += 512) {
        const float* pp = pts + (b * N_ + n) * 3;
        float x = pp[0], y = pp[1], z = pp[2];
        pts4[n] = make_float4(x, y, z, NEGH * (x * x + y * y + z * z));
    }
    if (tid < T_) {
        const float* tp = trans + (b * T_ + tid) * 3;
        float x = tp[0], y = tp[1], z = tp[2];
        tr4[tid] = make_float4(x, y, z, x * x + y * y + z * z);
    }
    __syncthreads();

    int laneA = tid & 31;
    int mtk0  = tid >> 5;
    int mt0   = mtk0 >> 2;
    int k80   = mtk0 & 3;
    int r0    = mt0 * 16 + (laneA >> 2);
    int cA0   = k80 * 8 + (laneA & 3);

    float4 pA[2][2];
    pA[0][0] = pts4[n0 + r0];
    pA[0][1] = pts4[n0 + r0 + 8];
    pA[1][0] = pts4[n0 + r0 + 64];
    pA[1][1] = pts4[n0 + r0 + 72];

    float sums[4] = {0.0f, 0.0f, 0.0f, 0.0f};
    size_t ebase = (size_t)(b * 8 + nt) * 32 * 1024;

    for (int kcl = 0; kcl < 16; ++kcl) {
        int kc = kh * 16 + kcl;
        int m = kc * 32 + cA0;
        float4 q0 = pts4[m];
        float4 q1 = pts4[m + 4];
        #pragma unroll
        for (int s = 0; s < 2; ++s) {
            float4 p0 = pA[s][0], p1 = pA[s][1];
            float d00 = fmaf(p0.z, q0.z, fmaf(p0.y, q0.y, p0.x * q0.x));
            float d10 = fmaf(p1.z, q0.z, fmaf(p1.y, q0.y, p1.x * q0.x));
            float d01 = fmaf(p0.z, q1.z, fmaf(p0.y, q1.y, p0.x * q1.x));
            float d11 = fmaf(p1.z, q1.z, fmaf(p1.y, q1.y, p1.x * q1.x));
            float e00 = ex2f(fmaf(d00, L2E, p0.w + q0.w));
            float e10 = ex2f(fmaf(d10, L2E, p1.w + q0.w));
            float e01 = ex2f(fmaf(d01, L2E, p0.w + q1.w));
            float e11 = ex2f(fmaf(d11, L2E, p1.w + q1.w));
            sums[s * 2]     += e00 + e01;
            sums[s * 2 + 1] += e10 + e11;
            g_E4[ebase + (size_t)kc * 1024 + tid + s * 512] =
                make_float4(to_tf32(e00), to_tf32(e10), to_tf32(e01), to_tf32(e11));
        }
    }

    int col = k80 * 4 + (laneA & 3);
    red[(r0     ) * 17 + col] = sums[0];
    red[(r0 +  8) * 17 + col] = sums[1];
    red[(r0 + 64) * 17 + col] = sums[2];
    red[(r0 + 72) * 17 + col] = sums[3];
    __syncthreads();

    if (tid < 128) {
        float rs = 0.0f;
        #pragma unroll
        for (int c = 0; c < 16; ++c) rs += red[tid * 17 + c];
        g_rspart[kh][b * N_ + n0 + tid] = rs;
        if (kh == 0) {
            float4 pn = pts4[n0 + tid];
            #pragma unroll
            for (int t = 0; t < T_; ++t) {
                float4 tv = tr4[t];
                float ptd = fmaf(pn.z, tv.z, fmaf(pn.y, tv.y, pn.x * tv.x));
                g_cf[(b * N_ + n0 + tid) * T_ + t] = __expf(-ptd - 0.5f * tv.w);
                g_u [(b * N_ + n0 + tid) * T_ + t] = __expf(ptd);
            }
        }
    }
}

// ---------------- K1: Ht via mma.sync tf32, output in B-fragment chunk order ---
// grid 256: b=bx>>5, mt=(bx>>2)&7, ct=bx&3.  Tile M128 x N128 x K64.
// 256 threads = 8 warps, grid 2(M) x 4(N), warp tile 64x32.
// dyn smem 69632: w_s[128][68] + kBs[64][136]; later reused as canonical [128][132]
#define WS_STRIDE 68
#define KB_STRIDE 136
#define HC_STRIDE 132
__global__ __launch_bounds__(256) void k_H(const float* __restrict__ func) {
    extern __shared__ float sm[];
    float* w_s = sm;                        // [128][68] = 34816 B
    float* kBs = sm + 128 * WS_STRIDE;      // [64][136] = 34816 B
    __shared__ float rinv[128];

    int bx = blockIdx.x;
    int b  = bx >> 5;
    int mt = (bx >> 2) & 7;
    int ct = bx & 3;
    int m0 = mt * 128, c0 = ct * 128;
    int tid = threadIdx.x;
    int lane = tid & 31, wid = tid >> 5;
    int mw = wid & 1, nw = wid >> 1;

    if (tid < 128) {
        int idx = b * N_ + m0 + tid;
        rinv[tid] = 1.0f / (g_rspart[0][idx] + g_rspart[1][idx]);
    }
    __syncthreads();

    for (int i = tid; i < 128 * 16; i += 256) {
        int m = i >> 4, c4 = i & 15;
        float4 v = *(const float4*)(func + (b * N_ + m0 + m) * CIN + c4 * 4);
        float r = rinv[m];
        v.x = to_tf32(v.x * r); v.y = to_tf32(v.y * r);
        v.z = to_tf32(v.z * r); v.w = to_tf32(v.w * r);
        *(float4*)(w_s + m * WS_STRIDE + c4 * 4) = v;
    }
    for (int i = tid; i < 64 * 32; i += 256) {
        int c = i >> 5, j = i & 31;
        float4 v = *(const float4*)(g_kB + c * COLS + c0 + j * 4);
        v.x = to_tf32(v.x); v.y = to_tf32(v.y);
        v.z = to_tf32(v.z); v.w = to_tf32(v.w);
        *(float4*)(kBs + c * KB_STRIDE + j * 4) = v;
    }
    __syncthreads();

    float c_[4][4][4];
    #pragma unroll
    for (int i = 0; i < 4; ++i)
        #pragma unroll
        for (int j = 0; j < 4; ++j)
            #pragma unroll
            for (int q = 0; q < 4; ++q) c_[i][j][q] = 0.0f;

    int ar = (lane >> 2), ac = (lane & 3);
    #pragma unroll
    for (int k8 = 0; k8 < 8; ++k8) {
        uint32_t a[4][4];
        #pragma unroll
        for (int mi = 0; mi < 4; ++mi) {
            int row = mw * 64 + mi * 16 + ar;
            int col = k8 * 8 + ac;
            a[mi][0] = __float_as_uint(w_s[row * WS_STRIDE + col]);
            a[mi][1] = __float_as_uint(w_s[(row + 8) * WS_STRIDE + col]);
            a[mi][2] = __float_as_uint(w_s[row * WS_STRIDE + col + 4]);
            a[mi][3] = __float_as_uint(w_s[(row + 8) * WS_STRIDE + col + 4]);
        }
        uint32_t bv[4][2];
        #pragma unroll
        for (int nj = 0; nj < 4; ++nj) {
            int kk = k8 * 8 + ac;
            int col = nw * 32 + nj * 8 + ar;
            bv[nj][0] = __float_as_uint(kBs[kk * KB_STRIDE + col]);
            bv[nj][1] = __float_as_uint(kBs[(kk + 4) * KB_STRIDE + col]);
        }
        #pragma unroll
        for (int mi = 0; mi < 4; ++mi)
            #pragma unroll
            for (int nj = 0; nj < 4; ++nj)
                mma1688(c_[mi][nj], a[mi], bv[nj]);
    }
    __syncthreads();   // staging dead; reuse smem as canonical tile

    #pragma unroll
    for (int mi = 0; mi < 4; ++mi)
        #pragma unroll
        for (int nj = 0; nj < 4; ++nj)
            #pragma unroll
            for (int q = 0; q < 4; ++q) {
                int row = mw * 64 + mi * 16 + ar + ((q >> 1) * 8);
                int col = nw * 32 + nj * 8 + ac * 2 + (q & 1);
                sm[row * HC_STRIDE + col] = c_[mi][nj][q];
            }
    __syncthreads();

    // round-4 proven epilogue, sourcing from canonical smem
    int ty = tid >> 4, tx = tid & 15;
    int jt_g = ct * 16 + tx;
    int t = jt_g >> 3;
    float cf_i[8];
    #pragma unroll
    for (int i = 0; i < 8; ++i)
        cf_i[i] = g_cf[(b * N_ + m0 + ty * 8 + i) * T_ + t];

    int ch  = jt_g >> 5;
    int jtl = jt_g & 31;
    int m8  = mt * 16 + ty;
    int kc  = m8 >> 2;
    int k8b = m8 & 3;
    float* base = g_Ht +
        (size_t)((((b * 2 + ch) * 32 + kc) * 4 + k8b) * 32 + jtl) * 64;

    #pragma unroll
    for (int jj = 0; jj < 8; ++jj) {
        float v[8];
        #pragma unroll
        for (int i = 0; i < 8; ++i)
            v[i] = to_tf32(sm[(ty * 8 + i) * HC_STRIDE + tx * 8 + jj] * cf_i[i]);
        float* dst = base + jj * 8;
        *(float4*)(dst)     = make_float4(v[0], v[4], v[1], v[5]);
        *(float4*)(dst + 4) = make_float4(v[2], v[6], v[3], v[7]);
    }
}

// ---------------- K2: cp.async HMMA tf32 GEMM, 2 CTA/SM, fold u, write planes --
// grid 256: b=bx>>5, nt=(bx>>2)&7, ch=bx&3.  M128 x N128 x K1024, 256 threads.
// 8 warps grid 2(M) x 4(N), warp tile 64x32. dyn smem: 3x16KB A + 3x16KB B = 96KB
__global__ __launch_bounds__(256, 2) void k_main() {
    extern __shared__ float sm[];
    uint32_t sbase = smem_u32(sm);

    int bx = blockIdx.x;
    int b  = bx >> 5;
    int nt = (bx >> 2) & 7;
    int ch = bx & 3;
    int ch2 = ch >> 1, chH = ch & 1;
    int n0 = nt * 128;
    int tid = threadIdx.x;
    int wid = tid >> 5, lane = tid & 31;
    int mw = wid & 1, nw = wid >> 1;

    const float4* EA = g_E4 + (size_t)(b * 8 + nt) * 32768;
    const float4* HB = (const float4*)g_Ht + (size_t)(b * 2 + ch2) * 65536 + chH * 256;
    uint32_t sA = sbase;              // 3 x 16384 B
    uint32_t sB = sbase + 49152;      // 3 x 16384 B

    auto issue = [&](int s) {
        int buf = s % 3;
        uint32_t da = sA + buf * 16384 + tid * 16;
        const float4* ga = EA + (size_t)s * 1024 + tid;
        uint32_t db = sB + buf * 16384 + tid * 16;
        #pragma unroll
        for (int p = 0; p < 4; ++p) {
            cp16(da + p * 4096, ga + p * 256);
            cp16(db + p * 4096, HB + (size_t)s * 2048 + p * 512 + tid);
        }
        CP_COMMIT();
    };

    issue(0); issue(1);

    float c_[4][4][4];
    #pragma unroll
    for (int i = 0; i < 4; ++i)
        #pragma unroll
        for (int j = 0; j < 4; ++j)
            #pragma unroll
            for (int q = 0; q < 4; ++q) c_[i][j][q] = 0.0f;

    for (int kc = 0; kc < 32; ++kc) {
        if (kc < 30) { CP_WAIT(1); } else { CP_WAIT(0); }
        __syncthreads();

        int buf = kc % 3;
        const float* Ac = sm + buf * 4096;
        const float* Bc = sm + 12288 + buf * 4096;

        #pragma unroll
        for (int k8 = 0; k8 < 4; ++k8) {
            uint32_t a[4][4];
            #pragma unroll
            for (int mi = 0; mi < 4; ++mi) {
                int mt = mw * 4 + mi;
                uint4 av = *(const uint4*)(Ac + ((mt * 4 + k8) * 32 + lane) * 4);
                a[mi][0] = av.x; a[mi][1] = av.y; a[mi][2] = av.z; a[mi][3] = av.w;
            }
            uint32_t bv[4][2];
            #pragma unroll
            for (int nj = 0; nj < 4; ++nj) {
                uint2 u = *(const uint2*)(Bc + ((k8 * 16 + nw * 4 + nj) * 32 + lane) * 2);
                bv[nj][0] = u.x; bv[nj][1] = u.y;
            }
            #pragma unroll
            for (int mi = 0; mi < 4; ++mi)
                #pragma unroll
                for (int nj = 0; nj < 4; ++nj)
                    mma1688(c_[mi][nj], a[mi], bv[nj]);
        }

        if (kc < 30) issue(kc + 2);
    }

    // epilogue: fold u_t[n], write plane t (unique writer per (t,n,o))
    int t = ch * 2 + (nw >> 1);
    int obase = (nw & 1) * 32 + (lane & 3) * 2;
    #pragma unroll
    for (int mi = 0; mi < 4; ++mi) {
        #pragma unroll
        for (int ro = 0; ro < 2; ++ro) {
            int n = n0 + mw * 64 + mi * 16 + (lane >> 2) + ro * 8;
            float u = g_u[(b * N_ + n) * T_ + t];
            float* dst = g_preT[t] + (size_t)(b * N_ + n) * CO + obase;
            #pragma unroll
            for (int nj = 0; nj < 4; ++nj) {
                float2 v;
                v.x = c_[mi][nj][ro * 2 + 0] * u;
                v.y = c_[mi][nj][ro * 2 + 1] * u;
                *(float2*)(dst + nj * 8) = v;
            }
        }
    }
}

// ---------------- K3: sum 8 planes + BN partial stats ----------------
__global__ __launch_bounds__(256) void k_stats() {
    __shared__ float sh[256], sh2[256];
    int blk = blockIdx.x;       // 64 blocks, 128 rows each
    int o  = threadIdx.x & 63;
    int rg = threadIdx.x >> 6;
    int r0 = blk * 128;

    float s = 0.0f, s2 = 0.0f;
    for (int r = r0 + rg; r < r0 + 128; r += 4) {
        float p = 0.0f;
        #pragma unroll
        for (int t = 0; t < T_; ++t) p += g_preT[t][r * CO + o];
        g_pre[r * CO + o] = p;
        s += p; s2 += p * p;
    }
    sh[threadIdx.x] = s; sh2[threadIdx.x] = s2;
    __syncthreads();
    if (rg == 0) {
        float ts  = s  + sh [o + 64] + sh [o + 128] + sh [o + 192];
        float ts2 = s2 + sh2[o + 64] + sh2[o + 128] + sh2[o + 192];
        g_part [blk * 64 + o] = ts;
        g_part2[blk * 64 + o] = ts2;
    }
}

// ---------------- K4: finalize (redundant per block) + apply BN + ReLU ----------
__global__ __launch_bounds__(256) void k_apply(float* __restrict__ out,
                                               const float* __restrict__ gamma,
                                               const float* __restrict__ beta) {
    __shared__ float ssum[256], ssum2[256];
    __shared__ float sscale[64], sbias[64];
    int tid = threadIdx.x;
    int o = tid & 63, g = tid >> 6;

    float s = 0.0f, s2 = 0.0f;
    for (int i = g; i < 64; i += 4) {
        s  += g_part [i * 64 + o];
        s2 += g_part2[i * 64 + o];
    }
    ssum[tid] = s; ssum2[tid] = s2;
    __syncthreads();
    if (tid < 64) {
        float ts  = ssum [o] + ssum [o + 64] + ssum [o + 128] + ssum [o + 192];
        float ts2 = ssum2[o] + ssum2[o + 64] + ssum2[o + 128] + ssum2[o + 192];
        float inv = 1.0f / (float)NB;
        float mean = ts * inv;
        float var = ts2 * inv - mean * mean;
        float sc = gamma[o] * rsqrtf(var + 1e-5f);
        sscale[o] = sc;
        sbias[o]  = beta[o] - mean * sc;
    }
    __syncthreads();

    int idx = blockIdx.x * 256 + tid;
    int e0 = idx * 4;
    int o0 = e0 & 63;
    float4 p = *(const float4*)(g_pre + e0);
    float4 r;
    r.x = fmaxf(fmaf(p.x, sscale[o0 + 0], sbias[o0 + 0]), 0.0f);
    r.y = fmaxf(fmaf(p.y, sscale[o0 + 1], sbias[o0 + 1]), 0.0f);
    r.z = fmaxf(fmaf(p.z, sscale[o0 + 2], sbias[o0 + 2]), 0.0f);
    r.w = fmaxf(fmaf(p.w, sscale[o0 + 3], sbias[o0 + 3]), 0.0f);
    *(float4*)(out + e0) = r;
}

// ---------------- launch ----------------
extern "C" void kernel_launch(void* const* d_in, const int* in_sizes, int n_in,
                              void* d_out, int out_size) {
    (void)in_sizes; (void)n_in; (void)out_size;
    const float* pts   = (const float*)d_in[0];
    const float* trans = (const float*)d_in[1];
    const float* func  = (const float*)d_in[2];
    const float* kt    = (const float*)d_in[3];
    const float* gamma = (const float*)d_in[4];
    const float* beta  = (const float*)d_in[5];
    float* out = (float*)d_out;

    cudaFuncSetAttribute(k_main, cudaFuncAttributeMaxDynamicSharedMemorySize, 98304);
    cudaFuncSetAttribute(k_H,    cudaFuncAttributeMaxDynamicSharedMemorySize, 69632);

    k_transpose<<<128, 256>>>(kt);
    k_prepE<<<128, 512>>>(pts, trans);
    k_H<<<256, 256, 69632>>>(func);
    k_main<<<256, 256, 98304>>>();
    k_stats<<<64, 256>>>();
    k_apply<<<512, 256>>>(out, gamma, beta);
}

// round 6
// speedup vs baseline: 2.8326x; 1.0312x over previous
#include <cuda_runtime.h>
#include <cstdint>

#define B_    8
#define N_    1024
#define T_    8
#define CIN   64
#define CO    64
#define COLS  512          // T_ * CO
#define NB    (B_ * N_)    // 8192
#define L2E   1.4426950408889634f     // log2(e)
#define NEGH  (-0.72134752044448170f) // -0.5*log2(e)

// ---------------- scratch (static device arrays; no allocation) ----------------
static __device__ __align__(16) float g_rspart[2][NB];      // rowsum partials (k-halves)
static __device__ __align__(16) float g_cf[NB * T_];        // [b][n][t] exp(-ptd - tsq/2)
static __device__ __align__(16) float g_u [NB * T_];        // [b][n][t] exp(+ptd)
static __device__ __align__(16) float g_kB[CIN * COLS];     // [c][t*64+o]
// E in A-fragment chunk order: [b][nt(8)][kc(32)][mt(8)][k8(4)][lane(32)] float4
static __device__ __align__(16) float4 g_E4[B_ * 8 * 32 * 1024];
// Ht in B-fragment chunk order: [b][ch2(2)][kc(32)][k8(4)][jtl(32)][lane(32)][2]
static __device__ __align__(16) float g_Ht[B_ * 2 * 32 * 4 * 32 * 32 * 2];
static __device__ __align__(16) float g_preT[T_][NB * CO];  // per-t planes
static __device__ __align__(16) float g_pre[NB * CO];
static __device__ __align__(16) float g_part [64 * CO];
static __device__ __align__(16) float g_part2[64 * CO];

// ---------------- helpers ----------------
__device__ __forceinline__ float to_tf32(float x) {
    float r;
    asm("cvt.rna.tf32.f32 %0, %1;" : "=f"(r) : "f"(x));
    return r;
}
__device__ __forceinline__ float ex2f(float x) {
    float r;
    asm("ex2.approx.ftz.f32 %0, %1;" : "=f"(r) : "f"(x));
    return r;
}
__device__ __forceinline__ uint32_t smem_u32(const void* p) {
    uint32_t a;
    asm("{ .reg .u64 t; cvta.to.shared.u64 t, %1; cvt.u32.u64 %0, t; }" : "=r"(a) : "l"(p));
    return a;
}
__device__ __forceinline__ void cp16(uint32_t s, const void* g) {
    asm volatile("cp.async.cg.shared.global [%0], [%1], 16;" :: "r"(s), "l"(g) : "memory");
}
#define CP_COMMIT() asm volatile("cp.async.commit_group;" ::: "memory")
#define CP_WAIT(n)  asm volatile("cp.async.wait_group %0;" :: "n"(n) : "memory")

// mma.sync m16n8k8 tf32 (baseline PTX)
__device__ __forceinline__ void mma1688(float* c, const uint32_t* a, const uint32_t* b2) {
    asm volatile(
        "mma.sync.aligned.m16n8k8.row.col.f32.tf32.tf32.f32 "
        "{%0,%1,%2,%3}, {%4,%5,%6,%7}, {%8,%9}, {%0,%1,%2,%3};"
        : "+f"(c[0]), "+f"(c[1]), "+f"(c[2]), "+f"(c[3])
        : "r"(a[0]), "r"(a[1]), "r"(a[2]), "r"(a[3]), "r"(b2[0]), "r"(b2[1]));
}

// ---------------- K0a: transpose k_tensor [o][c][t] -> kB [c][t*64+o] ----------
__global__ void k_transpose(const float* __restrict__ kt) {
    int i = blockIdx.x * 256 + threadIdx.x;
    if (i < CIN * COLS) {
        int c = i >> 9;
        int t = (i >> 6) & 7;
        int o = i & 63;
        g_kB[i] = kt[(o * CIN + c) * T_ + t];
    }
}

// ---------------- K0b: generate E (fragment order) + rowsum partials + cf/u ----
__global__ __launch_bounds__(512) void k_prepE(const float* __restrict__ pts,
                                               const float* __restrict__ trans) {
    __shared__ float4 pts4[N_];
    __shared__ float4 tr4[T_];
    __shared__ float red[128 * 17];

    int bx = blockIdx.x;
    int b  = bx >> 4;
    int nt = (bx >> 1) & 7;
    int kh = bx & 1;
    int n0 = nt * 128;
    int tid = threadIdx.x;

    for (int n = tid; n < N_; n += 512) {
        const float* pp = pts + (b * N_ + n) * 3;
        float x = pp[0], y = pp[1], z = pp[2];
        pts4[n] = make_float4(x, y, z, NEGH * (x * x + y * y + z * z));
    }
    if (tid < T_) {
        const float* tp = trans + (b * T_ + tid) * 3;
        float x = tp[0], y = tp[1], z = tp[2];
        tr4[tid] = make_float4(x, y, z, x * x + y * y + z * z);
    }
    __syncthreads();

    int laneA = tid & 31;
    int mtk0  = tid >> 5;
    int mt0   = mtk0 >> 2;
    int k80   = mtk0 & 3;
    int r0    = mt0 * 16 + (laneA >> 2);
    int cA0   = k80 * 8 + (laneA & 3);

    float4 pA[2][2];
    pA[0][0] = pts4[n0 + r0];
    pA[0][1] = pts4[n0 + r0 + 8];
    pA[1][0] = pts4[n0 + r0 + 64];
    pA[1][1] = pts4[n0 + r0 + 72];

    float sums[4] = {0.0f, 0.0f, 0.0f, 0.0f};
    size_t ebase = (size_t)(b * 8 + nt) * 32 * 1024;

    for (int kcl = 0; kcl < 16; ++kcl) {
        int kc = kh * 16 + kcl;
        int m = kc * 32 + cA0;
        float4 q0 = pts4[m];
        float4 q1 = pts4[m + 4];
        #pragma unroll
        for (int s = 0; s < 2; ++s) {
            float4 p0 = pA[s][0], p1 = pA[s][1];
            float d00 = fmaf(p0.z, q0.z, fmaf(p0.y, q0.y, p0.x * q0.x));
            float d10 = fmaf(p1.z, q0.z, fmaf(p1.y, q0.y, p1.x * q0.x));
            float d01 = fmaf(p0.z, q1.z, fmaf(p0.y, q1.y, p0.x * q1.x));
            float d11 = fmaf(p1.z, q1.z, fmaf(p1.y, q1.y, p1.x * q1.x));
            float e00 = ex2f(fmaf(d00, L2E, p0.w + q0.w));
            float e10 = ex2f(fmaf(d10, L2E, p1.w + q0.w));
            float e01 = ex2f(fmaf(d01, L2E, p0.w + q1.w));
            float e11 = ex2f(fmaf(d11, L2E, p1.w + q1.w));
            sums[s * 2]     += e00 + e01;
            sums[s * 2 + 1] += e10 + e11;
            g_E4[ebase + (size_t)kc * 1024 + tid + s * 512] =
                make_float4(to_tf32(e00), to_tf32(e10), to_tf32(e01), to_tf32(e11));
        }
    }

    int col = k80 * 4 + (laneA & 3);
    red[(r0     ) * 17 + col] = sums[0];
    red[(r0 +  8) * 17 + col] = sums[1];
    red[(r0 + 64) * 17 + col] = sums[2];
    red[(r0 + 72) * 17 + col] = sums[3];
    __syncthreads();

    if (tid < 128) {
        float rs = 0.0f;
        #pragma unroll
        for (int c = 0; c < 16; ++c) rs += red[tid * 17 + c];
        g_rspart[kh][b * N_ + n0 + tid] = rs;
        if (kh == 0) {
            float4 pn = pts4[n0 + tid];
            #pragma unroll
            for (int t = 0; t < T_; ++t) {
                float4 tv = tr4[t];
                float ptd = fmaf(pn.z, tv.z, fmaf(pn.y, tv.y, pn.x * tv.x));
                g_cf[(b * N_ + n0 + tid) * T_ + t] = __expf(-ptd - 0.5f * tv.w);
                g_u [(b * N_ + n0 + tid) * T_ + t] = __expf(ptd);
            }
        }
    }
}

// ---------------- K1: Ht via mma.sync tf32, output in B-fragment chunk order ---
#define WS_STRIDE 68
#define KB_STRIDE 136
#define HC_STRIDE 132
__global__ __launch_bounds__(256) void k_H(const float* __restrict__ func) {
    extern __shared__ float sm[];
    float* w_s = sm;                        // [128][68]
    float* kBs = sm + 128 * WS_STRIDE;      // [64][136]
    __shared__ float rinv[128];

    int bx = blockIdx.x;
    int b  = bx >> 5;
    int mt = (bx >> 2) & 7;
    int ct = bx & 3;
    int m0 = mt * 128, c0 = ct * 128;
    int tid = threadIdx.x;
    int lane = tid & 31, wid = tid >> 5;
    int mw = wid & 1, nw = wid >> 1;

    if (tid < 128) {
        int idx = b * N_ + m0 + tid;
        rinv[tid] = 1.0f / (g_rspart[0][idx] + g_rspart[1][idx]);
    }
    __syncthreads();

    for (int i = tid; i < 128 * 16; i += 256) {
        int m = i >> 4, c4 = i & 15;
        float4 v = *(const float4*)(func + (b * N_ + m0 + m) * CIN + c4 * 4);
        float r = rinv[m];
        v.x = to_tf32(v.x * r); v.y = to_tf32(v.y * r);
        v.z = to_tf32(v.z * r); v.w = to_tf32(v.w * r);
        *(float4*)(w_s + m * WS_STRIDE + c4 * 4) = v;
    }
    for (int i = tid; i < 64 * 32; i += 256) {
        int c = i >> 5, j = i & 31;
        float4 v = *(const float4*)(g_kB + c * COLS + c0 + j * 4);
        v.x = to_tf32(v.x); v.y = to_tf32(v.y);
        v.z = to_tf32(v.z); v.w = to_tf32(v.w);
        *(float4*)(kBs + c * KB_STRIDE + j * 4) = v;
    }
    __syncthreads();

    float c_[4][4][4];
    #pragma unroll
    for (int i = 0; i < 4; ++i)
        #pragma unroll
        for (int j = 0; j < 4; ++j)
            #pragma unroll
            for (int q = 0; q < 4; ++q) c_[i][j][q] = 0.0f;

    int ar = (lane >> 2), ac = (lane & 3);
    #pragma unroll
    for (int k8 = 0; k8 < 8; ++k8) {
        uint32_t a[4][4];
        #pragma unroll
        for (int mi = 0; mi < 4; ++mi) {
            int row = mw * 64 + mi * 16 + ar;
            int col = k8 * 8 + ac;
            a[mi][0] = __float_as_uint(w_s[row * WS_STRIDE + col]);
            a[mi][1] = __float_as_uint(w_s[(row + 8) * WS_STRIDE + col]);
            a[mi][2] = __float_as_uint(w_s[row * WS_STRIDE + col + 4]);
            a[mi][3] = __float_as_uint(w_s[(row + 8) * WS_STRIDE + col + 4]);
        }
        uint32_t bv[4][2];
        #pragma unroll
        for (int nj = 0; nj < 4; ++nj) {
            int kk = k8 * 8 + ac;
            int col = nw * 32 + nj * 8 + ar;
            bv[nj][0] = __float_as_uint(kBs[kk * KB_STRIDE + col]);
            bv[nj][1] = __float_as_uint(kBs[(kk + 4) * KB_STRIDE + col]);
        }
        #pragma unroll
        for (int mi = 0; mi < 4; ++mi)
            #pragma unroll
            for (int nj = 0; nj < 4; ++nj)
                mma1688(c_[mi][nj], a[mi], bv[nj]);
    }
    __syncthreads();

    #pragma unroll
    for (int mi = 0; mi < 4; ++mi)
        #pragma unroll
        for (int nj = 0; nj < 4; ++nj)
            #pragma unroll
            for (int q = 0; q < 4; ++q) {
                int row = mw * 64 + mi * 16 + ar + ((q >> 1) * 8);
                int col = nw * 32 + nj * 8 + ac * 2 + (q & 1);
                sm[row * HC_STRIDE + col] = c_[mi][nj][q];
            }
    __syncthreads();

    int ty = tid >> 4, tx = tid & 15;
    int jt_g = ct * 16 + tx;
    int t = jt_g >> 3;
    float cf_i[8];
    #pragma unroll
    for (int i = 0; i < 8; ++i)
        cf_i[i] = g_cf[(b * N_ + m0 + ty * 8 + i) * T_ + t];

    int ch  = jt_g >> 5;
    int jtl = jt_g & 31;
    int m8  = mt * 16 + ty;
    int kc  = m8 >> 2;
    int k8b = m8 & 3;
    float* base = g_Ht +
        (size_t)((((b * 2 + ch) * 32 + kc) * 4 + k8b) * 32 + jtl) * 64;

    #pragma unroll
    for (int jj = 0; jj < 8; ++jj) {
        float v[8];
        #pragma unroll
        for (int i = 0; i < 8; ++i)
            v[i] = to_tf32(sm[(ty * 8 + i) * HC_STRIDE + tx * 8 + jj] * cf_i[i]);
        float* dst = base + jj * 8;
        *(float4*)(dst)     = make_float4(v[0], v[4], v[1], v[5]);
        *(float4*)(dst + 4) = make_float4(v[2], v[6], v[3], v[7]);
    }
}

// ---------------- K2: cp.async HMMA tf32 GEMM, warp tile 64x64, write planes ---
// grid 128: b=bx>>4, nt=(bx>>1)&7, ch=bx&1.  CTA M128 x N256 x K1024, 256 thr.
// 8 warps grid 2(M) x 4(N), warp tile 64x64 (128 accum regs/thread).
// dyn smem: A 3x16KB + B 3x32KB = 147456 B (1 CTA/SM, single wave).
__global__ __launch_bounds__(256, 1) void k_main() {
    extern __shared__ float sm[];
    uint32_t sbase = smem_u32(sm);

    int bx = blockIdx.x;
    int b  = bx >> 4;
    int nt = (bx >> 1) & 7;
    int ch = bx & 1;
    int n0 = nt * 128;
    int tid = threadIdx.x;
    int wid = tid >> 5, lane = tid & 31;
    int mw = wid & 1, nw = wid >> 1;

    const float4* EA = g_E4 + (size_t)(b * 8 + nt) * 32768;
    const float4* HB = (const float4*)g_Ht + (size_t)(b * 2 + ch) * 65536;
    uint32_t sA = sbase;              // 3 x 16384 B
    uint32_t sB = sbase + 49152;      // 3 x 32768 B

    auto issue = [&](int s) {
        int buf = s % 3;
        uint32_t da = sA + buf * 16384 + tid * 16;
        const float4* ga = EA + (size_t)s * 1024 + tid;
        #pragma unroll
        for (int p = 0; p < 4; ++p)
            cp16(da + p * 4096, ga + p * 256);
        uint32_t db = sB + buf * 32768 + tid * 16;
        const float4* gb = HB + (size_t)s * 2048 + tid;
        #pragma unroll
        for (int p = 0; p < 8; ++p)
            cp16(db + p * 4096, gb + p * 256);
        CP_COMMIT();
    };

    issue(0); issue(1);

    float c_[4][8][4];
    #pragma unroll
    for (int i = 0; i < 4; ++i)
        #pragma unroll
        for (int j = 0; j < 8; ++j)
            #pragma unroll
            for (int q = 0; q < 4; ++q) c_[i][j][q] = 0.0f;

    for (int kc = 0; kc < 32; ++kc) {
        if (kc < 30) { CP_WAIT(1); } else { CP_WAIT(0); }
        __syncthreads();

        int buf = kc % 3;
        const float* Ac = sm + buf * 4096;
        const float* Bc = sm + 12288 + buf * 8192;

        #pragma unroll
        for (int k8 = 0; k8 < 4; ++k8) {
            uint32_t a[4][4];
            #pragma unroll
            for (int mi = 0; mi < 4; ++mi) {
                int mt = mw * 4 + mi;
                uint4 av = *(const uint4*)(Ac + ((mt * 4 + k8) * 32 + lane) * 4);
                a[mi][0] = av.x; a[mi][1] = av.y; a[mi][2] = av.z; a[mi][3] = av.w;
            }
            uint32_t bv[8][2];
            #pragma unroll
            for (int nj = 0; nj < 8; ++nj) {
                uint2 u = *(const uint2*)(Bc + ((k8 * 32 + nw * 8 + nj) * 32 + lane) * 2);
                bv[nj][0] = u.x; bv[nj][1] = u.y;
            }
            #pragma unroll
            for (int mi = 0; mi < 4; ++mi)
                #pragma unroll
                for (int nj = 0; nj < 8; ++nj)
                    mma1688(c_[mi][nj], a[mi], bv[nj]);
        }

        if (kc < 30) issue(kc + 2);
    }

    // epilogue: fold u_t[n], write plane t (one t per warp; unique writers)
    int t = ch * 4 + nw;
    int obase = (lane & 3) * 2;
    #pragma unroll
    for (int mi = 0; mi < 4; ++mi) {
        #pragma unroll
        for (int ro = 0; ro < 2; ++ro) {
            int n = n0 + mw * 64 + mi * 16 + (lane >> 2) + ro * 8;
            float u = g_u[(b * N_ + n) * T_ + t];
            float* dst = g_preT[t] + (size_t)(b * N_ + n) * CO + obase;
            #pragma unroll
            for (int nj = 0; nj < 8; ++nj) {
                float2 v;
                v.x = c_[mi][nj][ro * 2 + 0] * u;
                v.y = c_[mi][nj][ro * 2 + 1] * u;
                *(float2*)(dst + nj * 8) = v;
            }
        }
    }
}

// ---------------- K3: sum 8 planes + BN partial stats ----------------
__global__ __launch_bounds__(256) void k_stats() {
    __shared__ float sh[256], sh2[256];
    int blk = blockIdx.x;
    int o  = threadIdx.x & 63;
    int rg = threadIdx.x >> 6;
    int r0 = blk * 128;

    float s = 0.0f, s2 = 0.0f;
    for (int r = r0 + rg; r < r0 + 128; r += 4) {
        float p = 0.0f;
        #pragma unroll
        for (int t = 0; t < T_; ++t) p += g_preT[t][r * CO + o];
        g_pre[r * CO + o] = p;
        s += p; s2 += p * p;
    }
    sh[threadIdx.x] = s; sh2[threadIdx.x] = s2;
    __syncthreads();
    if (rg == 0) {
        float ts  = s  + sh [o + 64] + sh [o + 128] + sh [o + 192];
        float ts2 = s2 + sh2[o + 64] + sh2[o + 128] + sh2[o + 192];
        g_part [blk * 64 + o] = ts;
        g_part2[blk * 64 + o] = ts2;
    }
}

// ---------------- K4: finalize (redundant per block) + apply BN + ReLU ----------
__global__ __launch_bounds__(256) void k_apply(float* __restrict__ out,
                                               const float* __restrict__ gamma,
                                               const float* __restrict__ beta) {
    __shared__ float ssum[256], ssum2[256];
    __shared__ float sscale[64], sbias[64];
    int tid = threadIdx.x;
    int o = tid & 63, g = tid >> 6;

    float s = 0.0f, s2 = 0.0f;
    for (int i = g; i < 64; i += 4) {
        s  += g_part [i * 64 + o];
        s2 += g_part2[i * 64 + o];
    }
    ssum[tid] = s; ssum2[tid] = s2;
    __syncthreads();
    if (tid < 64) {
        float ts  = ssum [o] + ssum [o + 64] + ssum [o + 128] + ssum [o + 192];
        float ts2 = ssum2[o] + ssum2[o + 64] + ssum2[o + 128] + ssum2[o + 192];
        float inv = 1.0f / (float)NB;
        float mean = ts * inv;
        float var = ts2 * inv - mean * mean;
        float sc = gamma[o] * rsqrtf(var + 1e-5f);
        sscale[o] = sc;
        sbias[o]  = beta[o] - mean * sc;
    }
    __syncthreads();

    int idx = blockIdx.x * 256 + tid;
    int e0 = idx * 4;
    int o0 = e0 & 63;
    float4 p = *(const float4*)(g_pre + e0);
    float4 r;
    r.x = fmaxf(fmaf(p.x, sscale[o0 + 0], sbias[o0 + 0]), 0.0f);
    r.y = fmaxf(fmaf(p.y, sscale[o0 + 1], sbias[o0 + 1]), 0.0f);
    r.z = fmaxf(fmaf(p.z, sscale[o0 + 2], sbias[o0 + 2]), 0.0f);
    r.w = fmaxf(fmaf(p.w, sscale[o0 + 3], sbias[o0 + 3]), 0.0f);
    *(float4*)(out + e0) = r;
}

// ---------------- launch ----------------
extern "C" void kernel_launch(void* const* d_in, const int* in_sizes, int n_in,
                              void* d_out, int out_size) {
    (void)in_sizes; (void)n_in; (void)out_size;
    const float* pts   = (const float*)d_in[0];
    const float* trans = (const float*)d_in[1];
    const float* func  = (const float*)d_in[2];
    const float* kt    = (const float*)d_in[3];
    const float* gamma = (const float*)d_in[4];
    const float* beta  = (const float*)d_in[5];
    float* out = (float*)d_out;

    cudaFuncSetAttribute(k_main, cudaFuncAttributeMaxDynamicSharedMemorySize, 147456);
    cudaFuncSetAttribute(k_H,    cudaFuncAttributeMaxDynamicSharedMemorySize, 69632);

    k_transpose<<<128, 256>>>(kt);
    k_prepE<<<128, 512>>>(pts, trans);
    k_H<<<256, 256, 69632>>>(func);
    k_main<<<128, 256, 147456>>>();
    k_stats<<<64, 256>>>();
    k_apply<<<512, 256>>>(out, gamma, beta);
}

// round 7
// speedup vs baseline: 3.0869x; 1.0898x over previous
#include <cuda_runtime.h>
#include <cstdint>

#define B_    8
#define N_    1024
#define T_    8
#define CIN   64
#define CO    64
#define COLS  512          // T_ * CO
#define NB    (B_ * N_)    // 8192
#define L2E   1.4426950408889634f     // log2(e)
#define NEGH  (-0.72134752044448170f) // -0.5*log2(e)

// ---------------- scratch (static device arrays; no allocation) ----------------
static __device__ __align__(16) float g_rspart[2][NB];      // rowsum partials (k-halves)
static __device__ __align__(16) float g_cf[NB * T_];        // [b][n][t] exp(-ptd - tsq/2)
static __device__ __align__(16) float g_u [NB * T_];        // [b][n][t] exp(+ptd)
static __device__ __align__(16) float g_kB[CIN * COLS];     // [c][t*64+o]
// E in A-fragment chunk order: [b][nt(8)][kc(32)][mt(8)][k8(4)][lane(32)] float4
static __device__ __align__(16) float4 g_E4[B_ * 8 * 32 * 1024];
// Ht in B-fragment chunk order: [b][ch2(2)][kc(32)][k8(4)][jtl(32)][lane(32)][2]
static __device__ __align__(16) float g_Ht[B_ * 2 * 32 * 4 * 32 * 32 * 2];
static __device__ __align__(16) float g_preP[4][NB * CO];   // per-ch partial planes
static __device__ __align__(16) float g_pre[NB * CO];
static __device__ __align__(16) float g_part [64 * CO];
static __device__ __align__(16) float g_part2[64 * CO];

// ---------------- helpers ----------------
__device__ __forceinline__ float to_tf32(float x) {
    float r;
    asm("cvt.rna.tf32.f32 %0, %1;" : "=f"(r) : "f"(x));
    return r;
}
__device__ __forceinline__ float ex2f(float x) {
    float r;
    asm("ex2.approx.ftz.f32 %0, %1;" : "=f"(r) : "f"(x));
    return r;
}
__device__ __forceinline__ uint32_t smem_u32(const void* p) {
    uint32_t a;
    asm("{ .reg .u64 t; cvta.to.shared.u64 t, %1; cvt.u32.u64 %0, t; }" : "=r"(a) : "l"(p));
    return a;
}
__device__ __forceinline__ void cp16(uint32_t s, const void* g) {
    asm volatile("cp.async.cg.shared.global [%0], [%1], 16;" :: "r"(s), "l"(g) : "memory");
}
#define CP_COMMIT() asm volatile("cp.async.commit_group;" ::: "memory")
#define CP_WAIT(n)  asm volatile("cp.async.wait_group %0;" :: "n"(n) : "memory")

// mma.sync m16n8k8 tf32 (baseline PTX)
__device__ __forceinline__ void mma1688(float* c, const uint32_t* a, const uint32_t* b2) {
    asm volatile(
        "mma.sync.aligned.m16n8k8.row.col.f32.tf32.tf32.f32 "
        "{%0,%1,%2,%3}, {%4,%5,%6,%7}, {%8,%9}, {%0,%1,%2,%3};"
        : "+f"(c[0]), "+f"(c[1]), "+f"(c[2]), "+f"(c[3])
        : "r"(a[0]), "r"(a[1]), "r"(a[2]), "r"(a[3]), "r"(b2[0]), "r"(b2[1]));
}

// ---------------- K0a: transpose k_tensor [o][c][t] -> kB [c][t*64+o] ----------
__global__ void k_transpose(const float* __restrict__ kt) {
    int i = blockIdx.x * 256 + threadIdx.x;
    if (i < CIN * COLS) {
        int c = i >> 9;
        int t = (i >> 6) & 7;
        int o = i & 63;
        g_kB[i] = kt[(o * CIN + c) * T_ + t];
    }
}

// ---------------- K0b: generate E (fragment order) + rowsum partials + cf/u ----
__global__ __launch_bounds__(512) void k_prepE(const float* __restrict__ pts,
                                               const float* __restrict__ trans) {
    __shared__ float4 pts4[N_];
    __shared__ float4 tr4[T_];
    __shared__ float red[128 * 17];

    int bx = blockIdx.x;
    int b  = bx >> 4;
    int nt = (bx >> 1) & 7;
    int kh = bx & 1;
    int n0 = nt * 128;
    int tid = threadIdx.x;

    for (int n = tid; n < N_; n += 512) {
        const float* pp = pts + (b * N_ + n) * 3;
        float x = pp[0], y = pp[1], z = pp[2];
        pts4[n] = make_float4(x, y, z, NEGH * (x * x + y * y + z * z));
    }
    if (tid < T_) {
        const float* tp = trans + (b * T_ + tid) * 3;
        float x = tp[0], y = tp[1], z = tp[2];
        tr4[tid] = make_float4(x, y, z, x * x + y * y + z * z);
    }
    __syncthreads();

    int laneA = tid & 31;
    int mtk0  = tid >> 5;
    int mt0   = mtk0 >> 2;
    int k80   = mtk0 & 3;
    int r0    = mt0 * 16 + (laneA >> 2);
    int cA0   = k80 * 8 + (laneA & 3);

    float4 pA[2][2];
    pA[0][0] = pts4[n0 + r0];
    pA[0][1] = pts4[n0 + r0 + 8];
    pA[1][0] = pts4[n0 + r0 + 64];
    pA[1][1] = pts4[n0 + r0 + 72];

    float sums[4] = {0.0f, 0.0f, 0.0f, 0.0f};
    size_t ebase = (size_t)(b * 8 + nt) * 32 * 1024;

    for (int kcl = 0; kcl < 16; ++kcl) {
        int kc = kh * 16 + kcl;
        int m = kc * 32 + cA0;
        float4 q0 = pts4[m];
        float4 q1 = pts4[m + 4];
        #pragma unroll
        for (int s = 0; s < 2; ++s) {
            float4 p0 = pA[s][0], p1 = pA[s][1];
            float d00 = fmaf(p0.z, q0.z, fmaf(p0.y, q0.y, p0.x * q0.x));
            float d10 = fmaf(p1.z, q0.z, fmaf(p1.y, q0.y, p1.x * q0.x));
            float d01 = fmaf(p0.z, q1.z, fmaf(p0.y, q1.y, p0.x * q1.x));
            float d11 = fmaf(p1.z, q1.z, fmaf(p1.y, q1.y, p1.x * q1.x));
            float e00 = ex2f(fmaf(d00, L2E, p0.w + q0.w));
            float e10 = ex2f(fmaf(d10, L2E, p1.w + q0.w));
            float e01 = ex2f(fmaf(d01, L2E, p0.w + q1.w));
            float e11 = ex2f(fmaf(d11, L2E, p1.w + q1.w));
            sums[s * 2]     += e00 + e01;
            sums[s * 2 + 1] += e10 + e11;
            g_E4[ebase + (size_t)kc * 1024 + tid + s * 512] =
                make_float4(to_tf32(e00), to_tf32(e10), to_tf32(e01), to_tf32(e11));
        }
    }

    int col = k80 * 4 + (laneA & 3);
    red[(r0     ) * 17 + col] = sums[0];
    red[(r0 +  8) * 17 + col] = sums[1];
    red[(r0 + 64) * 17 + col] = sums[2];
    red[(r0 + 72) * 17 + col] = sums[3];
    __syncthreads();

    if (tid < 128) {
        float rs = 0.0f;
        #pragma unroll
        for (int c = 0; c < 16; ++c) rs += red[tid * 17 + c];
        g_rspart[kh][b * N_ + n0 + tid] = rs;
        if (kh == 0) {
            float4 pn = pts4[n0 + tid];
            #pragma unroll
            for (int t = 0; t < T_; ++t) {
                float4 tv = tr4[t];
                float ptd = fmaf(pn.z, tv.z, fmaf(pn.y, tv.y, pn.x * tv.x));
                g_cf[(b * N_ + n0 + tid) * T_ + t] = __expf(-ptd - 0.5f * tv.w);
                g_u [(b * N_ + n0 + tid) * T_ + t] = __expf(ptd);
            }
        }
    }
}

// ---------------- K1: Ht via mma.sync tf32, output in B-fragment chunk order ---
#define WS_STRIDE 68
#define KB_STRIDE 136
#define HC_STRIDE 132
__global__ __launch_bounds__(256) void k_H(const float* __restrict__ func) {
    extern __shared__ float sm[];
    float* w_s = sm;                        // [128][68]
    float* kBs = sm + 128 * WS_STRIDE;      // [64][136]
    __shared__ float rinv[128];

    int bx = blockIdx.x;
    int b  = bx >> 5;
    int mt = (bx >> 2) & 7;
    int ct = bx & 3;
    int m0 = mt * 128, c0 = ct * 128;
    int tid = threadIdx.x;
    int lane = tid & 31, wid = tid >> 5;
    int mw = wid & 1, nw = wid >> 1;

    if (tid < 128) {
        int idx = b * N_ + m0 + tid;
        rinv[tid] = 1.0f / (g_rspart[0][idx] + g_rspart[1][idx]);
    }
    __syncthreads();

    for (int i = tid; i < 128 * 16; i += 256) {
        int m = i >> 4, c4 = i & 15;
        float4 v = *(const float4*)(func + (b * N_ + m0 + m) * CIN + c4 * 4);
        float r = rinv[m];
        v.x = to_tf32(v.x * r); v.y = to_tf32(v.y * r);
        v.z = to_tf32(v.z * r); v.w = to_tf32(v.w * r);
        *(float4*)(w_s + m * WS_STRIDE + c4 * 4) = v;
    }
    for (int i = tid; i < 64 * 32; i += 256) {
        int c = i >> 5, j = i & 31;
        float4 v = *(const float4*)(g_kB + c * COLS + c0 + j * 4);
        v.x = to_tf32(v.x); v.y = to_tf32(v.y);
        v.z = to_tf32(v.z); v.w = to_tf32(v.w);
        *(float4*)(kBs + c * KB_STRIDE + j * 4) = v;
    }
    __syncthreads();

    float c_[4][4][4];
    #pragma unroll
    for (int i = 0; i < 4; ++i)
        #pragma unroll
        for (int j = 0; j < 4; ++j)
            #pragma unroll
            for (int q = 0; q < 4; ++q) c_[i][j][q] = 0.0f;

    int ar = (lane >> 2), ac = (lane & 3);
    #pragma unroll
    for (int k8 = 0; k8 < 8; ++k8) {
        uint32_t a[4][4];
        #pragma unroll
        for (int mi = 0; mi < 4; ++mi) {
            int row = mw * 64 + mi * 16 + ar;
            int col = k8 * 8 + ac;
            a[mi][0] = __float_as_uint(w_s[row * WS_STRIDE + col]);
            a[mi][1] = __float_as_uint(w_s[(row + 8) * WS_STRIDE + col]);
            a[mi][2] = __float_as_uint(w_s[row * WS_STRIDE + col + 4]);
            a[mi][3] = __float_as_uint(w_s[(row + 8) * WS_STRIDE + col + 4]);
        }
        uint32_t bv[4][2];
        #pragma unroll
        for (int nj = 0; nj < 4; ++nj) {
            int kk = k8 * 8 + ac;
            int col = nw * 32 + nj * 8 + ar;
            bv[nj][0] = __float_as_uint(kBs[kk * KB_STRIDE + col]);
            bv[nj][1] = __float_as_uint(kBs[(kk + 4) * KB_STRIDE + col]);
        }
        #pragma unroll
        for (int mi = 0; mi < 4; ++mi)
            #pragma unroll
            for (int nj = 0; nj < 4; ++nj)
                mma1688(c_[mi][nj], a[mi], bv[nj]);
    }
    __syncthreads();

    #pragma unroll
    for (int mi = 0; mi < 4; ++mi)
        #pragma unroll
        for (int nj = 0; nj < 4; ++nj)
            #pragma unroll
            for (int q = 0; q < 4; ++q) {
                int row = mw * 64 + mi * 16 + ar + ((q >> 1) * 8);
                int col = nw * 32 + nj * 8 + ac * 2 + (q & 1);
                sm[row * HC_STRIDE + col] = c_[mi][nj][q];
            }
    __syncthreads();

    int ty = tid >> 4, tx = tid & 15;
    int jt_g = ct * 16 + tx;
    int t = jt_g >> 3;
    float cf_i[8];
    #pragma unroll
    for (int i = 0; i < 8; ++i)
        cf_i[i] = g_cf[(b * N_ + m0 + ty * 8 + i) * T_ + t];

    int ch  = jt_g >> 5;
    int jtl = jt_g & 31;
    int m8  = mt * 16 + ty;
    int kc  = m8 >> 2;
    int k8b = m8 & 3;
    float* base = g_Ht +
        (size_t)((((b * 2 + ch) * 32 + kc) * 4 + k8b) * 32 + jtl) * 64;

    #pragma unroll
    for (int jj = 0; jj < 8; ++jj) {
        float v[8];
        #pragma unroll
        for (int i = 0; i < 8; ++i)
            v[i] = to_tf32(sm[(ty * 8 + i) * HC_STRIDE + tx * 8 + jj] * cf_i[i]);
        float* dst = base + jj * 8;
        *(float4*)(dst)     = make_float4(v[0], v[4], v[1], v[5]);
        *(float4*)(dst + 4) = make_float4(v[2], v[6], v[3], v[7]);
    }
}

// ---------------- K2: cp.async HMMA tf32 GEMM, 2 CTA/SM, smem t-reduce ---------
// grid 256: b=bx>>5, nt=(bx>>2)&7, ch=bx&3.  CTA M128 x N128 x K1024, 128 thr.
// 4 warps grid 2(M) x 2(N), warp tile 64x64.  smem: A 3x16KB + B 3x16KB = 96KB.
#define RST 68
__global__ __launch_bounds__(128, 2) void k_main() {
    extern __shared__ float sm[];
    uint32_t sbase = smem_u32(sm);

    int bx = blockIdx.x;
    int b  = bx >> 5;
    int nt = (bx >> 2) & 7;
    int ch = bx & 3;
    int ch2 = ch >> 1, chH = ch & 1;
    int n0 = nt * 128;
    int tid = threadIdx.x;
    int wid = tid >> 5, lane = tid & 31;
    int mw = wid & 1, nw = wid >> 1;

    const float4* EA = g_E4 + (size_t)(b * 8 + nt) * 32768;
    const float4* HB = (const float4*)g_Ht + (size_t)(b * 2 + ch2) * 65536 + chH * 256;
    uint32_t sA = sbase;              // 3 x 16384 B
    uint32_t sB = sbase + 49152;      // 3 x 16384 B

    auto issue = [&](int s) {
        int buf = s % 3;
        uint32_t da = sA + buf * 16384 + tid * 16;
        const float4* ga = EA + (size_t)s * 1024 + tid;
        #pragma unroll
        for (int p = 0; p < 8; ++p)
            cp16(da + p * 2048, ga + p * 128);
        uint32_t db = sB + buf * 16384;
        #pragma unroll
        for (int p = 0; p < 8; ++p) {
            int idx = p * 128 + tid;
            int k8 = idx >> 8, rem = idx & 255;   // rem = jtlL*16 + l4
            cp16(db + idx * 16, HB + (size_t)s * 2048 + k8 * 512 + rem);
        }
        CP_COMMIT();
    };

    issue(0); issue(1);

    float c_[4][8][4];
    #pragma unroll
    for (int i = 0; i < 4; ++i)
        #pragma unroll
        for (int j = 0; j < 8; ++j)
            #pragma unroll
            for (int q = 0; q < 4; ++q) c_[i][j][q] = 0.0f;

    for (int kc = 0; kc < 32; ++kc) {
        if (kc < 30) { CP_WAIT(1); } else { CP_WAIT(0); }
        __syncthreads();

        int buf = kc % 3;
        const float* Ac = sm + buf * 4096;
        const float* Bc = sm + 12288 + buf * 4096;

        #pragma unroll
        for (int k8 = 0; k8 < 4; ++k8) {
            uint32_t a[4][4];
            #pragma unroll
            for (int mi = 0; mi < 4; ++mi) {
                int mt = mw * 4 + mi;
                uint4 av = *(const uint4*)(Ac + ((mt * 4 + k8) * 32 + lane) * 4);
                a[mi][0] = av.x; a[mi][1] = av.y; a[mi][2] = av.z; a[mi][3] = av.w;
            }
            uint32_t bv[8][2];
            #pragma unroll
            for (int nj = 0; nj < 8; ++nj) {
                uint2 u = *(const uint2*)(Bc + ((k8 * 16 + nw * 8 + nj) * 32 + lane) * 2);
                bv[nj][0] = u.x; bv[nj][1] = u.y;
            }
            #pragma unroll
            for (int mi = 0; mi < 4; ++mi)
                #pragma unroll
                for (int nj = 0; nj < 8; ++nj)
                    mma1688(c_[mi][nj], a[mi], bv[nj]);
        }

        if (kc < 30) issue(kc + 2);
    }

    // ---- epilogue: scale by u_t, reduce the CTA's two t's in smem, write plane
    __syncthreads();   // mainloop smem dead
    int t = ch * 2 + nw;
    float* red = sm + mw * 64 * RST;

    if (nw == 0) {
        #pragma unroll
        for (int mi = 0; mi < 4; ++mi) {
            #pragma unroll
            for (int ro = 0; ro < 2; ++ro) {
                int rloc = mi * 16 + (lane >> 2) + ro * 8;
                float u = g_u[(b * N_ + n0 + mw * 64 + rloc) * T_ + t];
                #pragma unroll
                for (int nj = 0; nj < 8; ++nj) {
                    float2 v;
                    v.x = c_[mi][nj][ro * 2 + 0] * u;
                    v.y = c_[mi][nj][ro * 2 + 1] * u;
                    *(float2*)(red + rloc * RST + nj * 8 + (lane & 3) * 2) = v;
                }
            }
        }
    }
    __syncthreads();
    if (nw == 1) {
        #pragma unroll
        for (int mi = 0; mi < 4; ++mi) {
            #pragma unroll
            for (int ro = 0; ro < 2; ++ro) {
                int rloc = mi * 16 + (lane >> 2) + ro * 8;
                int n = n0 + mw * 64 + rloc;
                float u = g_u[(b * N_ + n) * T_ + t];
                float* dst = g_preP[ch] + (size_t)(b * N_ + n) * CO + (lane & 3) * 2;
                #pragma unroll
                for (int nj = 0; nj < 8; ++nj) {
                    float2 p = *(const float2*)(red + rloc * RST + nj * 8 + (lane & 3) * 2);
                    float2 v;
                    v.x = fmaf(c_[mi][nj][ro * 2 + 0], u, p.x);
                    v.y = fmaf(c_[mi][nj][ro * 2 + 1], u, p.y);
                    *(float2*)(dst + nj * 8) = v;
                }
            }
        }
    }
}

// ---------------- K3: sum 4 planes + BN partial stats ----------------
__global__ __launch_bounds__(256) void k_stats() {
    __shared__ float sh[256], sh2[256];
    int blk = blockIdx.x;
    int o  = threadIdx.x & 63;
    int rg = threadIdx.x >> 6;
    int r0 = blk * 128;

    float s = 0.0f, s2 = 0.0f;
    for (int r = r0 + rg; r < r0 + 128; r += 4) {
        float p = g_preP[0][r * CO + o] + g_preP[1][r * CO + o]
                + g_preP[2][r * CO + o] + g_preP[3][r * CO + o];
        g_pre[r * CO + o] = p;
        s += p; s2 += p * p;
    }
    sh[threadIdx.x] = s; sh2[threadIdx.x] = s2;
    __syncthreads();
    if (rg == 0) {
        float ts  = s  + sh [o + 64] + sh [o + 128] + sh [o + 192];
        float ts2 = s2 + sh2[o + 64] + sh2[o + 128] + sh2[o + 192];
        g_part [blk * 64 + o] = ts;
        g_part2[blk * 64 + o] = ts2;
    }
}

// ---------------- K4: finalize (redundant per block) + apply BN + ReLU ----------
__global__ __launch_bounds__(256) void k_apply(float* __restrict__ out,
                                               const float* __restrict__ gamma,
                                               const float* __restrict__ beta) {
    __shared__ float ssum[256], ssum2[256];
    __shared__ float sscale[64], sbias[64];
    int tid = threadIdx.x;
    int o = tid & 63, g = tid >> 6;

    float s = 0.0f, s2 = 0.0f;
    for (int i = g; i < 64; i += 4) {
        s  += g_part [i * 64 + o];
        s2 += g_part2[i * 64 + o];
    }
    ssum[tid] = s; ssum2[tid] = s2;
    __syncthreads();
    if (tid < 64) {
        float ts  = ssum [o] + ssum [o + 64] + ssum [o + 128] + ssum [o + 192];
        float ts2 = ssum2[o] + ssum2[o + 64] + ssum2[o + 128] + ssum2[o + 192];
        float inv = 1.0f / (float)NB;
        float mean = ts * inv;
        float var = ts2 * inv - mean * mean;
        float sc = gamma[o] * rsqrtf(var + 1e-5f);
        sscale[o] = sc;
        sbias[o]  = beta[o] - mean * sc;
    }
    __syncthreads();

    int idx = blockIdx.x * 256 + tid;
    int e0 = idx * 4;
    int o0 = e0 & 63;
    float4 p = *(const float4*)(g_pre + e0);
    float4 r;
    r.x = fmaxf(fmaf(p.x, sscale[o0 + 0], sbias[o0 + 0]), 0.0f);
    r.y = fmaxf(fmaf(p.y, sscale[o0 + 1], sbias[o0 + 1]), 0.0f);
    r.z = fmaxf(fmaf(p.z, sscale[o0 + 2], sbias[o0 + 2]), 0.0f);
    r.w = fmaxf(fmaf(p.w, sscale[o0 + 3], sbias[o0 + 3]), 0.0f);
    *(float4*)(out + e0) = r;
}

// ---------------- launch ----------------
extern "C" void kernel_launch(void* const* d_in, const int* in_sizes, int n_in,
                              void* d_out, int out_size) {
    (void)in_sizes; (void)n_in; (void)out_size;
    const float* pts   = (const float*)d_in[0];
    const float* trans = (const float*)d_in[1];
    const float* func  = (const float*)d_in[2];
    const float* kt    = (const float*)d_in[3];
    const float* gamma = (const float*)d_in[4];
    const float* beta  = (const float*)d_in[5];
    float* out = (float*)d_out;

    cudaFuncSetAttribute(k_main, cudaFuncAttributeMaxDynamicSharedMemorySize, 98304);
    cudaFuncSetAttribute(k_H,    cudaFuncAttributeMaxDynamicSharedMemorySize, 69632);

    k_transpose<<<128, 256>>>(kt);
    k_prepE<<<128, 512>>>(pts, trans);
    k_H<<<256, 256, 69632>>>(func);
    k_main<<<256, 128, 98304>>>();
    k_stats<<<64, 256>>>();
    k_apply<<<512, 256>>>(out, gamma, beta);
}

// round 8
// speedup vs baseline: 3.8963x; 1.2622x over previous
#include <cuda_runtime.h>
#include <cuda_fp16.h>
#include <cstdint>

#define B_    8
#define N_    1024
#define T_    8
#define CIN   64
#define CO    64
#define COLS  512          // T_ * CO
#define NB    (B_ * N_)    // 8192
#define L2E   1.4426950408889634f     // log2(e)
#define NEGH  (-0.72134752044448170f) // -0.5*log2(e)

// ---------------- scratch (static device arrays; no allocation) ----------------
static __device__ __align__(16) float g_rspart[2][NB];      // rowsum partials (k-halves)
static __device__ __align__(16) float g_cf[NB * T_];        // [b][n][t] exp(-ptd - tsq/2)
static __device__ __align__(16) float g_u [NB * T_];        // [b][n][t] exp(+ptd)
static __device__ __align__(16) float g_kB[CIN * COLS];     // [c][t*64+o]
// E as fp16 m16n8k16 A-fragments: [b][nt(8)][u(64)][mt(8)][lane(32)] uint4
static __device__ __align__(16) uint4 g_E4h[B_ * 8 * 64 * 256];
// Ht as fp16 B-fragments: [b][ch2(2)][u(64)][n8g(32)][lane(32)] uint2
static __device__ __align__(16) uint2 g_Hth[B_ * 2 * 64 * 32 * 32];
static __device__ __align__(16) float g_preP[4][NB * CO];   // per-ch partial planes
static __device__ __align__(16) float g_pre[NB * CO];
static __device__ __align__(16) float g_part [64 * CO];
static __device__ __align__(16) float g_part2[64 * CO];

// ---------------- helpers ----------------
__device__ __forceinline__ float to_tf32(float x) {
    float r;
    asm("cvt.rna.tf32.f32 %0, %1;" : "=f"(r) : "f"(x));
    return r;
}
__device__ __forceinline__ float ex2f(float x) {
    float r;
    asm("ex2.approx.ftz.f32 %0, %1;" : "=f"(r) : "f"(x));
    return r;
}
__device__ __forceinline__ uint32_t h2pack(float lo, float hi) {
    uint32_t r;
    asm("cvt.rn.f16x2.f32 %0, %1, %2;" : "=r"(r) : "f"(hi), "f"(lo));
    return r;
}
__device__ __forceinline__ uint32_t smem_u32(const void* p) {
    uint32_t a;
    asm("{ .reg .u64 t; cvta.to.shared.u64 t, %1; cvt.u32.u64 %0, t; }" : "=r"(a) : "l"(p));
    return a;
}
__device__ __forceinline__ void cp16(uint32_t s, const void* g) {
    asm volatile("cp.async.cg.shared.global [%0], [%1], 16;" :: "r"(s), "l"(g) : "memory");
}
#define CP_COMMIT() asm volatile("cp.async.commit_group;" ::: "memory")
#define CP_WAIT(n)  asm volatile("cp.async.wait_group %0;" :: "n"(n) : "memory")

// mma.sync m16n8k8 tf32 (k_H only)
__device__ __forceinline__ void mma1688(float* c, const uint32_t* a, const uint32_t* b2) {
    asm volatile(
        "mma.sync.aligned.m16n8k8.row.col.f32.tf32.tf32.f32 "
        "{%0,%1,%2,%3}, {%4,%5,%6,%7}, {%8,%9}, {%0,%1,%2,%3};"
        : "+f"(c[0]), "+f"(c[1]), "+f"(c[2]), "+f"(c[3])
        : "r"(a[0]), "r"(a[1]), "r"(a[2]), "r"(a[3]), "r"(b2[0]), "r"(b2[1]));
}
// mma.sync m16n8k16 fp16 with f32 accum (k_main)
__device__ __forceinline__ void mma16816(float* c, const uint4 a, const uint2 b) {
    asm volatile(
        "mma.sync.aligned.m16n8k16.row.col.f32.f16.f16.f32 "
        "{%0,%1,%2,%3}, {%4,%5,%6,%7}, {%8,%9}, {%0,%1,%2,%3};"
        : "+f"(c[0]), "+f"(c[1]), "+f"(c[2]), "+f"(c[3])
        : "r"(a.x), "r"(a.y), "r"(a.z), "r"(a.w), "r"(b.x), "r"(b.y));
}

// ---------------- K0a: transpose k_tensor [o][c][t] -> kB [c][t*64+o] ----------
__global__ void k_transpose(const float* __restrict__ kt) {
    int i = blockIdx.x * 256 + threadIdx.x;
    if (i < CIN * COLS) {
        int c = i >> 9;
        int t = (i >> 6) & 7;
        int o = i & 63;
        g_kB[i] = kt[(o * CIN + c) * T_ + t];
    }
}

// ---------------- K0b: generate E (fp16 A-fragments) + rowsum partials + cf/u --
// grid 128: b = bx>>4, nt = (bx>>1)&7, kh = bx&1 (u units kh*32 .. +31)
// 16 warps: warp w -> mt = w>>1, upar = w&1; lane: r = lane>>2, cq = (lane&3)*2
__global__ __launch_bounds__(512) void k_prepE(const float* __restrict__ pts,
                                               const float* __restrict__ trans) {
    __shared__ float4 pts4[N_];
    __shared__ float4 tr4[T_];
    __shared__ float red[128 * 9];

    int bx = blockIdx.x;
    int b  = bx >> 4;
    int nt = (bx >> 1) & 7;
    int kh = bx & 1;
    int n0 = nt * 128;
    int tid = threadIdx.x;

    for (int n = tid; n < N_; n += 512) {
        const float* pp = pts + (b * N_ + n) * 3;
        float x = pp[0], y = pp[1], z = pp[2];
        pts4[n] = make_float4(x, y, z, NEGH * (x * x + y * y + z * z));
    }
    if (tid < T_) {
        const float* tp = trans + (b * T_ + tid) * 3;
        float x = tp[0], y = tp[1], z = tp[2];
        tr4[tid] = make_float4(x, y, z, x * x + y * y + z * z);
    }
    __syncthreads();

    int lane = tid & 31;
    int w    = tid >> 5;
    int mt   = w >> 1;
    int upar = w & 1;
    int r    = lane >> 2;
    int cq   = (lane & 3) * 2;

    float4 pr  = pts4[n0 + mt * 16 + r];
    float4 pr8 = pts4[n0 + mt * 16 + r + 8];

    float sum_r = 0.0f, sum_r8 = 0.0f;
    uint4* ebase = g_E4h + (size_t)(b * 8 + nt) * 64 * 256;

    #pragma unroll 4
    for (int i = 0; i < 16; ++i) {
        int u = kh * 32 + upar + 2 * i;
        int m = u * 16 + cq;
        float4 q0 = pts4[m], q1 = pts4[m + 1];
        float4 q8 = pts4[m + 8], q9 = pts4[m + 9];

        float e_r_0  = ex2f(fmaf(fmaf(pr.z, q0.z, fmaf(pr.y, q0.y, pr.x * q0.x)), L2E, pr.w + q0.w));
        float e_r_1  = ex2f(fmaf(fmaf(pr.z, q1.z, fmaf(pr.y, q1.y, pr.x * q1.x)), L2E, pr.w + q1.w));
        float e_r_8  = ex2f(fmaf(fmaf(pr.z, q8.z, fmaf(pr.y, q8.y, pr.x * q8.x)), L2E, pr.w + q8.w));
        float e_r_9  = ex2f(fmaf(fmaf(pr.z, q9.z, fmaf(pr.y, q9.y, pr.x * q9.x)), L2E, pr.w + q9.w));
        float e_s_0  = ex2f(fmaf(fmaf(pr8.z, q0.z, fmaf(pr8.y, q0.y, pr8.x * q0.x)), L2E, pr8.w + q0.w));
        float e_s_1  = ex2f(fmaf(fmaf(pr8.z, q1.z, fmaf(pr8.y, q1.y, pr8.x * q1.x)), L2E, pr8.w + q1.w));
        float e_s_8  = ex2f(fmaf(fmaf(pr8.z, q8.z, fmaf(pr8.y, q8.y, pr8.x * q8.x)), L2E, pr8.w + q8.w));
        float e_s_9  = ex2f(fmaf(fmaf(pr8.z, q9.z, fmaf(pr8.y, q9.y, pr8.x * q9.x)), L2E, pr8.w + q9.w));

        sum_r  += (e_r_0 + e_r_1) + (e_r_8 + e_r_9);
        sum_r8 += (e_s_0 + e_s_1) + (e_s_8 + e_s_9);

        uint4 frag;
        frag.x = h2pack(e_r_0, e_r_1);   // a0: row r,   k cq, cq+1
        frag.y = h2pack(e_s_0, e_s_1);   // a1: row r+8
        frag.z = h2pack(e_r_8, e_r_9);   // a2: row r,   k cq+8, cq+9
        frag.w = h2pack(e_s_8, e_s_9);   // a3: row r+8
        ebase[(size_t)u * 256 + mt * 32 + lane] = frag;
    }

    int col = upar * 4 + (lane & 3);
    red[(mt * 16 + r    ) * 9 + col] = sum_r;
    red[(mt * 16 + r + 8) * 9 + col] = sum_r8;
    __syncthreads();

    if (tid < 128) {
        float rs = 0.0f;
        #pragma unroll
        for (int c = 0; c < 8; ++c) rs += red[tid * 9 + c];
        g_rspart[kh][b * N_ + n0 + tid] = rs;
        if (kh == 0) {
            float4 pn = pts4[n0 + tid];
            #pragma unroll
            for (int t = 0; t < T_; ++t) {
                float4 tv = tr4[t];
                float ptd = fmaf(pn.z, tv.z, fmaf(pn.y, tv.y, pn.x * tv.x));
                g_cf[(b * N_ + n0 + tid) * T_ + t] = __expf(-ptd - 0.5f * tv.w);
                g_u [(b * N_ + n0 + tid) * T_ + t] = __expf(ptd);
            }
        }
    }
}

// ---------------- K1: Ht via mma.sync tf32, packed to fp16 B-fragments ---------
#define WS_STRIDE 68
#define KB_STRIDE 136
#define HC_STRIDE 132
__global__ __launch_bounds__(256) void k_H(const float* __restrict__ func) {
    extern __shared__ float sm[];
    float* w_s = sm;                        // [128][68]
    float* kBs = sm + 128 * WS_STRIDE;      // [64][136]
    __shared__ float rinv[128];

    int bx = blockIdx.x;
    int b  = bx >> 5;
    int mt = (bx >> 2) & 7;
    int ct = bx & 3;
    int m0 = mt * 128, c0 = ct * 128;
    int tid = threadIdx.x;
    int lane = tid & 31, wid = tid >> 5;
    int mw = wid & 1, nw = wid >> 1;

    if (tid < 128) {
        int idx = b * N_ + m0 + tid;
        rinv[tid] = 1.0f / (g_rspart[0][idx] + g_rspart[1][idx]);
    }
    __syncthreads();

    for (int i = tid; i < 128 * 16; i += 256) {
        int m = i >> 4, c4 = i & 15;
        float4 v = *(const float4*)(func + (b * N_ + m0 + m) * CIN + c4 * 4);
        float r = rinv[m];
        v.x = to_tf32(v.x * r); v.y = to_tf32(v.y * r);
        v.z = to_tf32(v.z * r); v.w = to_tf32(v.w * r);
        *(float4*)(w_s + m * WS_STRIDE + c4 * 4) = v;
    }
    for (int i = tid; i < 64 * 32; i += 256) {
        int c = i >> 5, j = i & 31;
        float4 v = *(const float4*)(g_kB + c * COLS + c0 + j * 4);
        v.x = to_tf32(v.x); v.y = to_tf32(v.y);
        v.z = to_tf32(v.z); v.w = to_tf32(v.w);
        *(float4*)(kBs + c * KB_STRIDE + j * 4) = v;
    }
    __syncthreads();

    float c_[4][4][4];
    #pragma unroll
    for (int i = 0; i < 4; ++i)
        #pragma unroll
        for (int j = 0; j < 4; ++j)
            #pragma unroll
            for (int q = 0; q < 4; ++q) c_[i][j][q] = 0.0f;

    int ar = (lane >> 2), ac = (lane & 3);
    #pragma unroll
    for (int k8 = 0; k8 < 8; ++k8) {
        uint32_t a[4][4];
        #pragma unroll
        for (int mi = 0; mi < 4; ++mi) {
            int row = mw * 64 + mi * 16 + ar;
            int col = k8 * 8 + ac;
            a[mi][0] = __float_as_uint(w_s[row * WS_STRIDE + col]);
            a[mi][1] = __float_as_uint(w_s[(row + 8) * WS_STRIDE + col]);
            a[mi][2] = __float_as_uint(w_s[row * WS_STRIDE + col + 4]);
            a[mi][3] = __float_as_uint(w_s[(row + 8) * WS_STRIDE + col + 4]);
        }
        uint32_t bv[4][2];
        #pragma unroll
        for (int nj = 0; nj < 4; ++nj) {
            int kk = k8 * 8 + ac;
            int col = nw * 32 + nj * 8 + ar;
            bv[nj][0] = __float_as_uint(kBs[kk * KB_STRIDE + col]);
            bv[nj][1] = __float_as_uint(kBs[(kk + 4) * KB_STRIDE + col]);
        }
        #pragma unroll
        for (int mi = 0; mi < 4; ++mi)
            #pragma unroll
            for (int nj = 0; nj < 4; ++nj)
                mma1688(c_[mi][nj], a[mi], bv[nj]);
    }
    __syncthreads();

    #pragma unroll
    for (int mi = 0; mi < 4; ++mi)
        #pragma unroll
        for (int nj = 0; nj < 4; ++nj)
            #pragma unroll
            for (int q = 0; q < 4; ++q) {
                int row = mw * 64 + mi * 16 + ar + ((q >> 1) * 8);
                int col = nw * 32 + nj * 8 + ac * 2 + (q & 1);
                sm[row * HC_STRIDE + col] = c_[mi][nj][q];
            }
    __syncthreads();

    // pack to fp16 B-fragments: value (m_global=k, j_global=n)
    int ty = tid >> 4, tx = tid & 15;
    int jt_g = ct * 16 + tx;
    int t = jt_g >> 3;
    float cf_i[8];
    #pragma unroll
    for (int i = 0; i < 8; ++i)
        cf_i[i] = g_cf[(b * N_ + m0 + ty * 8 + i) * T_ + t];

    int ch2 = ct >> 1;
    int n8g = (ct & 1) * 16 + tx;
    int u   = mt * 8 + (ty >> 1);
    int sel = ty & 1;
    size_t base_idx = ((size_t)((b * 2 + ch2) * 64 + u) * 32 + n8g) * 32;
    char* hb = (char*)g_Hth;

    #pragma unroll
    for (int jj = 0; jj < 8; ++jj) {
        float v[8];
        #pragma unroll
        for (int i = 0; i < 8; ++i)
            v[i] = sm[(ty * 8 + i) * HC_STRIDE + tx * 8 + jj] * cf_i[i];
        #pragma unroll
        for (int ip = 0; ip < 4; ++ip) {
            uint32_t hv = h2pack(v[2 * ip], v[2 * ip + 1]);
            size_t idx = base_idx + jj * 4 + ip;
            *(uint32_t*)(hb + idx * 8 + sel * 4) = hv;
        }
    }
}

// ---------------- K2: cp.async fp16 HMMA GEMM, k-chunk 64, 2 CTA/SM ------------
// grid 256: b=bx>>5, nt=(bx>>2)&7, ch=bx&3.  CTA M128 x N128 x K1024, 128 thr.
// 4 warps grid 2(M) x 2(N), warp tile 64x64.  smem: A 3x16KB + B 3x16KB = 96KB.
#define RST 68
__global__ __launch_bounds__(128, 2) void k_main() {
    extern __shared__ float sm[];
    uint32_t sbase = smem_u32(sm);

    int bx = blockIdx.x;
    int b  = bx >> 5;
    int nt = (bx >> 2) & 7;
    int ch = bx & 3;
    int ch2 = ch >> 1, chH = ch & 1;
    int n0 = nt * 128;
    int tid = threadIdx.x;
    int wid = tid >> 5, lane = tid & 31;
    int mw = wid & 1, nw = wid >> 1;

    const char* EA = (const char*)(g_E4h + (size_t)(b * 8 + nt) * 64 * 256);
    const char* HB = (const char*)(g_Hth + (size_t)(b * 2 + ch2) * 64 * 1024) + chH * 4096;
    uint32_t sA = sbase;              // 3 x 16384 B
    uint32_t sB = sbase + 49152;      // 3 x 16384 B

    auto issue = [&](int s) {         // s = chunk of 64 k = 4 u-units
        int buf = s % 3;
        int u0 = s * 4;
        #pragma unroll
        for (int p = 0; p < 8; ++p) {
            int idx = p * 128 + tid;
            int ul = idx >> 8, rem = (idx & 255) * 16;
            cp16(sA + buf * 16384 + idx * 16, EA + (size_t)(u0 + ul) * 4096 + rem);
            cp16(sB + buf * 16384 + idx * 16, HB + (size_t)(u0 + ul) * 8192 + rem);
        }
        CP_COMMIT();
    };

    issue(0); issue(1);

    float c_[4][8][4];
    #pragma unroll
    for (int i = 0; i < 4; ++i)
        #pragma unroll
        for (int j = 0; j < 8; ++j)
            #pragma unroll
            for (int q = 0; q < 4; ++q) c_[i][j][q] = 0.0f;

    for (int kc = 0; kc < 16; ++kc) {
        if (kc < 14) { CP_WAIT(1); } else { CP_WAIT(0); }
        __syncthreads();

        int buf = kc % 3;
        const uint4* Au = (const uint4*)(sm) + buf * 1024;
        const uint2* Bu = (const uint2*)(sm + 12288) + buf * 2048;

        #pragma unroll
        for (int ul = 0; ul < 4; ++ul) {
            uint4 a[4];
            #pragma unroll
            for (int mi = 0; mi < 4; ++mi)
                a[mi] = Au[(ul * 8 + mw * 4 + mi) * 32 + lane];
            uint2 bv[8];
            #pragma unroll
            for (int nj = 0; nj < 8; ++nj)
                bv[nj] = Bu[(ul * 16 + nw * 8 + nj) * 32 + lane];
            #pragma unroll
            for (int mi = 0; mi < 4; ++mi)
                #pragma unroll
                for (int nj = 0; nj < 8; ++nj)
                    mma16816(c_[mi][nj], a[mi], bv[nj]);
        }

        if (kc < 14) issue(kc + 2);
    }

    // ---- epilogue: scale by u_t, reduce the CTA's two t's in smem, write plane
    __syncthreads();   // mainloop smem dead
    int t = ch * 2 + nw;
    float* red = sm + mw * 64 * RST;

    if (nw == 0) {
        #pragma unroll
        for (int mi = 0; mi < 4; ++mi) {
            #pragma unroll
            for (int ro = 0; ro < 2; ++ro) {
                int rloc = mi * 16 + (lane >> 2) + ro * 8;
                float u = g_u[(b * N_ + n0 + mw * 64 + rloc) * T_ + t];
                #pragma unroll
                for (int nj = 0; nj < 8; ++nj) {
                    float2 v;
                    v.x = c_[mi][nj][ro * 2 + 0] * u;
                    v.y = c_[mi][nj][ro * 2 + 1] * u;
                    *(float2*)(red + rloc * RST + nj * 8 + (lane & 3) * 2) = v;
                }
            }
        }
    }
    __syncthreads();
    if (nw == 1) {
        #pragma unroll
        for (int mi = 0; mi < 4; ++mi) {
            #pragma unroll
            for (int ro = 0; ro < 2; ++ro) {
                int rloc = mi * 16 + (lane >> 2) + ro * 8;
                int n = n0 + mw * 64 + rloc;
                float u = g_u[(b * N_ + n) * T_ + t];
                float* dst = g_preP[ch] + (size_t)(b * N_ + n) * CO + (lane & 3) * 2;
                #pragma unroll
                for (int nj = 0; nj < 8; ++nj) {
                    float2 p = *(const float2*)(red + rloc * RST + nj * 8 + (lane & 3) * 2);
                    float2 v;
                    v.x = fmaf(c_[mi][nj][ro * 2 + 0], u, p.x);
                    v.y = fmaf(c_[mi][nj][ro * 2 + 1], u, p.y);
                    *(float2*)(dst + nj * 8) = v;
                }
            }
        }
    }
}

// ---------------- K3: sum 4 planes + BN partial stats ----------------
__global__ __launch_bounds__(256) void k_stats() {
    __shared__ float sh[256], sh2[256];
    int blk = blockIdx.x;
    int o  = threadIdx.x & 63;
    int rg = threadIdx.x >> 6;
    int r0 = blk * 128;

    float s = 0.0f, s2 = 0.0f;
    for (int r = r0 + rg; r < r0 + 128; r += 4) {
        float p = g_preP[0][r * CO + o] + g_preP[1][r * CO + o]
                + g_preP[2][r * CO + o] + g_preP[3][r * CO + o];
        g_pre[r * CO + o] = p;
        s += p; s2 += p * p;
    }
    sh[threadIdx.x] = s; sh2[threadIdx.x] = s2;
    __syncthreads();
    if (rg == 0) {
        float ts  = s  + sh [o + 64] + sh [o + 128] + sh [o + 192];
        float ts2 = s2 + sh2[o + 64] + sh2[o + 128] + sh2[o + 192];
        g_part [blk * 64 + o] = ts;
        g_part2[blk * 64 + o] = ts2;
    }
}

// ---------------- K4: finalize (redundant per block) + apply BN + ReLU ----------
__global__ __launch_bounds__(256) void k_apply(float* __restrict__ out,
                                               const float* __restrict__ gamma,
                                               const float* __restrict__ beta) {
    __shared__ float ssum[256], ssum2[256];
    __shared__ float sscale[64], sbias[64];
    int tid = threadIdx.x;
    int o = tid & 63, g = tid >> 6;

    float s = 0.0f, s2 = 0.0f;
    for (int i = g; i < 64; i += 4) {
        s  += g_part [i * 64 + o];
        s2 += g_part2[i * 64 + o];
    }
    ssum[tid] = s; ssum2[tid] = s2;
    __syncthreads();
    if (tid < 64) {
        float ts  = ssum [o] + ssum [o + 64] + ssum [o + 128] + ssum [o + 192];
        float ts2 = ssum2[o] + ssum2[o + 64] + ssum2[o + 128] + ssum2[o + 192];
        float inv = 1.0f / (float)NB;
        float mean = ts * inv;
        float var = ts2 * inv - mean * mean;
        float sc = gamma[o] * rsqrtf(var + 1e-5f);
        sscale[o] = sc;
        sbias[o]  = beta[o] - mean * sc;
    }
    __syncthreads();

    int idx = blockIdx.x * 256 + tid;
    int e0 = idx * 4;
    int o0 = e0 & 63;
    float4 p = *(const float4*)(g_pre + e0);
    float4 r;
    r.x = fmaxf(fmaf(p.x, sscale[o0 + 0], sbias[o0 + 0]), 0.0f);
    r.y = fmaxf(fmaf(p.y, sscale[o0 + 1], sbias[o0 + 1]), 0.0f);
    r.z = fmaxf(fmaf(p.z, sscale[o0 + 2], sbias[o0 + 2]), 0.0f);
    r.w = fmaxf(fmaf(p.w, sscale[o0 + 3], sbias[o0 + 3]), 0.0f);
    *(float4*)(out + e0) = r;
}

// ---------------- launch ----------------
extern "C" void kernel_launch(void* const* d_in, const int* in_sizes, int n_in,
                              void* d_out, int out_size) {
    (void)in_sizes; (void)n_in; (void)out_size;
    const float* pts   = (const float*)d_in[0];
    const float* trans = (const float*)d_in[1];
    const float* func  = (const float*)d_in[2];
    const float* kt    = (const float*)d_in[3];
    const float* gamma = (const float*)d_in[4];
    const float* beta  = (const float*)d_in[5];
    float* out = (float*)d_out;

    cudaFuncSetAttribute(k_main, cudaFuncAttributeMaxDynamicSharedMemorySize, 98304);
    cudaFuncSetAttribute(k_H,    cudaFuncAttributeMaxDynamicSharedMemorySize, 69632);

    k_transpose<<<128, 256>>>(kt);
    k_prepE<<<128, 512>>>(pts, trans);
    k_H<<<256, 256, 69632>>>(func);
    k_main<<<256, 128, 98304>>>();
    k_stats<<<64, 256>>>();
    k_apply<<<512, 256>>>(out, gamma, beta);
}

// round 9
// speedup vs baseline: 4.4055x; 1.1307x over previous
#include <cuda_runtime.h>
#include <cuda_fp16.h>
#include <cstdint>

#define B_    8
#define N_    1024
#define T_    8
#define CIN   64
#define CO    64
#define COLS  512          // T_ * CO
#define NB    (B_ * N_)    // 8192
#define L2E   1.4426950408889634f     // log2(e)
#define NEGH  (-0.72134752044448170f) // -0.5*log2(e)

// ---------------- scratch (static device arrays; no allocation) ----------------
static __device__ __align__(16) float g_rspart[2][NB];      // rowsum partials (k-halves)
static __device__ __align__(16) float g_cf[NB * T_];        // [b][n][t] exp(-ptd - tsq/2)
static __device__ __align__(16) float g_u [NB * T_];        // [b][n][t] exp(+ptd)
static __device__ __align__(16) float g_kB[CIN * COLS];     // [c][t*64+o]
// E as fp16 m16n8k16 A-fragments: [b][nt(8)][u(64)][mt(8)][lane(32)] uint4
static __device__ __align__(16) uint4 g_E4h[B_ * 8 * 64 * 256];
// Ht as fp16 B-fragments: [b][ch2(2)][u(64)][n8g(32)][lane(32)] uint2
static __device__ __align__(16) uint2 g_Hth[B_ * 2 * 64 * 32 * 32];
static __device__ __align__(16) float g_preP[4][NB * CO];   // per-ch partial planes
static __device__ __align__(16) float g_pre[NB * CO];
static __device__ __align__(16) float g_part [128 * CO];
static __device__ __align__(16) float g_part2[128 * CO];
static __device__ int g_ctr;

// ---------------- helpers ----------------
__device__ __forceinline__ float to_tf32(float x) {
    float r;
    asm("cvt.rna.tf32.f32 %0, %1;" : "=f"(r) : "f"(x));
    return r;
}
__device__ __forceinline__ float ex2f(float x) {
    float r;
    asm("ex2.approx.ftz.f32 %0, %1;" : "=f"(r) : "f"(x));
    return r;
}
__device__ __forceinline__ uint32_t h2pack(float lo, float hi) {
    uint32_t r;
    asm("cvt.rn.f16x2.f32 %0, %1, %2;" : "=r"(r) : "f"(hi), "f"(lo));
    return r;
}
__device__ __forceinline__ uint32_t smem_u32(const void* p) {
    uint32_t a;
    asm("{ .reg .u64 t; cvta.to.shared.u64 t, %1; cvt.u32.u64 %0, t; }" : "=r"(a) : "l"(p));
    return a;
}
__device__ __forceinline__ void cp16(uint32_t s, const void* g) {
    asm volatile("cp.async.cg.shared.global [%0], [%1], 16;" :: "r"(s), "l"(g) : "memory");
}
#define CP_COMMIT() asm volatile("cp.async.commit_group;" ::: "memory")
#define CP_WAIT(n)  asm volatile("cp.async.wait_group %0;" :: "n"(n) : "memory")

// mma.sync m16n8k8 tf32 (k_H only)
__device__ __forceinline__ void mma1688(float* c, const uint32_t* a, const uint32_t* b2) {
    asm volatile(
        "mma.sync.aligned.m16n8k8.row.col.f32.tf32.tf32.f32 "
        "{%0,%1,%2,%3}, {%4,%5,%6,%7}, {%8,%9}, {%0,%1,%2,%3};"
        : "+f"(c[0]), "+f"(c[1]), "+f"(c[2]), "+f"(c[3])
        : "r"(a[0]), "r"(a[1]), "r"(a[2]), "r"(a[3]), "r"(b2[0]), "r"(b2[1]));
}
// mma.sync m16n8k16 fp16 with f32 accum (k_main)
__device__ __forceinline__ void mma16816(float* c, const uint4 a, const uint2 b) {
    asm volatile(
        "mma.sync.aligned.m16n8k16.row.col.f32.f16.f16.f32 "
        "{%0,%1,%2,%3}, {%4,%5,%6,%7}, {%8,%9}, {%0,%1,%2,%3};"
        : "+f"(c[0]), "+f"(c[1]), "+f"(c[2]), "+f"(c[3])
        : "r"(a.x), "r"(a.y), "r"(a.z), "r"(a.w), "r"(b.x), "r"(b.y));
}

// ---------------- K0: E gen (fp16 A-frags) + rowsum partials + cf/u + kB copy --
// grid 128: b = bx>>4, nt = (bx>>1)&7, kh = bx&1 (u units kh*32 .. +31)
__global__ __launch_bounds__(512) void k_prepE(const float* __restrict__ pts,
                                               const float* __restrict__ trans,
                                               const float* __restrict__ kt) {
    __shared__ float4 pts4[N_];
    __shared__ float4 tr4[T_];
    __shared__ float red[128 * 9];

    int bx = blockIdx.x;
    int b  = bx >> 4;
    int nt = (bx >> 1) & 7;
    int kh = bx & 1;
    int n0 = nt * 128;
    int tid = threadIdx.x;

    // folded k_transpose: blocks 0..15 copy kB slice (consumed by k_H next launch)
    if (bx < 16) {
        #pragma unroll
        for (int q = 0; q < 4; ++q) {
            int i = bx * 2048 + q * 512 + tid;
            int c = i >> 9;
            int t = (i >> 6) & 7;
            int o = i & 63;
            g_kB[i] = kt[(o * CIN + c) * T_ + t];
        }
    }

    for (int n = tid; n < N_; n += 512) {
        const float* pp = pts + (b * N_ + n) * 3;
        float x = pp[0], y = pp[1], z = pp[2];
        pts4[n] = make_float4(x, y, z, NEGH * (x * x + y * y + z * z));
    }
    if (tid < T_) {
        const float* tp = trans + (b * T_ + tid) * 3;
        float x = tp[0], y = tp[1], z = tp[2];
        tr4[tid] = make_float4(x, y, z, x * x + y * y + z * z);
    }
    __syncthreads();

    int lane = tid & 31;
    int w    = tid >> 5;
    int mt   = w >> 1;
    int upar = w & 1;
    int r    = lane >> 2;
    int cq   = (lane & 3) * 2;

    float4 pr  = pts4[n0 + mt * 16 + r];
    float4 pr8 = pts4[n0 + mt * 16 + r + 8];

    float sum_r = 0.0f, sum_r8 = 0.0f;
    uint4* ebase = g_E4h + (size_t)(b * 8 + nt) * 64 * 256;

    #pragma unroll 4
    for (int i = 0; i < 16; ++i) {
        int u = kh * 32 + upar + 2 * i;
        int m = u * 16 + cq;
        float4 q0 = pts4[m], q1 = pts4[m + 1];
        float4 q8 = pts4[m + 8], q9 = pts4[m + 9];

        float e_r_0  = ex2f(fmaf(fmaf(pr.z, q0.z, fmaf(pr.y, q0.y, pr.x * q0.x)), L2E, pr.w + q0.w));
        float e_r_1  = ex2f(fmaf(fmaf(pr.z, q1.z, fmaf(pr.y, q1.y, pr.x * q1.x)), L2E, pr.w + q1.w));
        float e_r_8  = ex2f(fmaf(fmaf(pr.z, q8.z, fmaf(pr.y, q8.y, pr.x * q8.x)), L2E, pr.w + q8.w));
        float e_r_9  = ex2f(fmaf(fmaf(pr.z, q9.z, fmaf(pr.y, q9.y, pr.x * q9.x)), L2E, pr.w + q9.w));
        float e_s_0  = ex2f(fmaf(fmaf(pr8.z, q0.z, fmaf(pr8.y, q0.y, pr8.x * q0.x)), L2E, pr8.w + q0.w));
        float e_s_1  = ex2f(fmaf(fmaf(pr8.z, q1.z, fmaf(pr8.y, q1.y, pr8.x * q1.x)), L2E, pr8.w + q1.w));
        float e_s_8  = ex2f(fmaf(fmaf(pr8.z, q8.z, fmaf(pr8.y, q8.y, pr8.x * q8.x)), L2E, pr8.w + q8.w));
        float e_s_9  = ex2f(fmaf(fmaf(pr8.z, q9.z, fmaf(pr8.y, q9.y, pr8.x * q9.x)), L2E, pr8.w + q9.w));

        sum_r  += (e_r_0 + e_r_1) + (e_r_8 + e_r_9);
        sum_r8 += (e_s_0 + e_s_1) + (e_s_8 + e_s_9);

        uint4 frag;
        frag.x = h2pack(e_r_0, e_r_1);
        frag.y = h2pack(e_s_0, e_s_1);
        frag.z = h2pack(e_r_8, e_r_9);
        frag.w = h2pack(e_s_8, e_s_9);
        ebase[(size_t)u * 256 + mt * 32 + lane] = frag;
    }

    int col = upar * 4 + (lane & 3);
    red[(mt * 16 + r    ) * 9 + col] = sum_r;
    red[(mt * 16 + r + 8) * 9 + col] = sum_r8;
    __syncthreads();

    if (tid < 128) {
        float rs = 0.0f;
        #pragma unroll
        for (int c = 0; c < 8; ++c) rs += red[tid * 9 + c];
        g_rspart[kh][b * N_ + n0 + tid] = rs;
        if (kh == 0) {
            float4 pn = pts4[n0 + tid];
            #pragma unroll
            for (int t = 0; t < T_; ++t) {
                float4 tv = tr4[t];
                float ptd = fmaf(pn.z, tv.z, fmaf(pn.y, tv.y, pn.x * tv.x));
                g_cf[(b * N_ + n0 + tid) * T_ + t] = __expf(-ptd - 0.5f * tv.w);
                g_u [(b * N_ + n0 + tid) * T_ + t] = __expf(ptd);
            }
        }
    }
}

// ---------------- K1: Ht via mma.sync tf32, packed to fp16 B-fragments ---------
#define WS_STRIDE 68
#define KB_STRIDE 136
#define HC_STRIDE 132
__global__ __launch_bounds__(256) void k_H(const float* __restrict__ func) {
    extern __shared__ float sm[];
    float* w_s = sm;                        // [128][68]
    float* kBs = sm + 128 * WS_STRIDE;      // [64][136]
    __shared__ float rinv[128];

    int bx = blockIdx.x;
    int b  = bx >> 5;
    int mt = (bx >> 2) & 7;
    int ct = bx & 3;
    int m0 = mt * 128, c0 = ct * 128;
    int tid = threadIdx.x;
    int lane = tid & 31, wid = tid >> 5;
    int mw = wid & 1, nw = wid >> 1;

    if (tid < 128) {
        int idx = b * N_ + m0 + tid;
        rinv[tid] = 1.0f / (g_rspart[0][idx] + g_rspart[1][idx]);
    }
    __syncthreads();

    for (int i = tid; i < 128 * 16; i += 256) {
        int m = i >> 4, c4 = i & 15;
        float4 v = *(const float4*)(func + (b * N_ + m0 + m) * CIN + c4 * 4);
        float r = rinv[m];
        v.x = to_tf32(v.x * r); v.y = to_tf32(v.y * r);
        v.z = to_tf32(v.z * r); v.w = to_tf32(v.w * r);
        *(float4*)(w_s + m * WS_STRIDE + c4 * 4) = v;
    }
    for (int i = tid; i < 64 * 32; i += 256) {
        int c = i >> 5, j = i & 31;
        float4 v = *(const float4*)(g_kB + c * COLS + c0 + j * 4);
        v.x = to_tf32(v.x); v.y = to_tf32(v.y);
        v.z = to_tf32(v.z); v.w = to_tf32(v.w);
        *(float4*)(kBs + c * KB_STRIDE + j * 4) = v;
    }
    __syncthreads();

    float c_[4][4][4];
    #pragma unroll
    for (int i = 0; i < 4; ++i)
        #pragma unroll
        for (int j = 0; j < 4; ++j)
            #pragma unroll
            for (int q = 0; q < 4; ++q) c_[i][j][q] = 0.0f;

    int ar = (lane >> 2), ac = (lane & 3);
    #pragma unroll
    for (int k8 = 0; k8 < 8; ++k8) {
        uint32_t a[4][4];
        #pragma unroll
        for (int mi = 0; mi < 4; ++mi) {
            int row = mw * 64 + mi * 16 + ar;
            int col = k8 * 8 + ac;
            a[mi][0] = __float_as_uint(w_s[row * WS_STRIDE + col]);
            a[mi][1] = __float_as_uint(w_s[(row + 8) * WS_STRIDE + col]);
            a[mi][2] = __float_as_uint(w_s[row * WS_STRIDE + col + 4]);
            a[mi][3] = __float_as_uint(w_s[(row + 8) * WS_STRIDE + col + 4]);
        }
        uint32_t bv[4][2];
        #pragma unroll
        for (int nj = 0; nj < 4; ++nj) {
            int kk = k8 * 8 + ac;
            int col = nw * 32 + nj * 8 + ar;
            bv[nj][0] = __float_as_uint(kBs[kk * KB_STRIDE + col]);
            bv[nj][1] = __float_as_uint(kBs[(kk + 4) * KB_STRIDE + col]);
        }
        #pragma unroll
        for (int mi = 0; mi < 4; ++mi)
            #pragma unroll
            for (int nj = 0; nj < 4; ++nj)
                mma1688(c_[mi][nj], a[mi], bv[nj]);
    }
    __syncthreads();

    #pragma unroll
    for (int mi = 0; mi < 4; ++mi)
        #pragma unroll
        for (int nj = 0; nj < 4; ++nj)
            #pragma unroll
            for (int q = 0; q < 4; ++q) {
                int row = mw * 64 + mi * 16 + ar + ((q >> 1) * 8);
                int col = nw * 32 + nj * 8 + ac * 2 + (q & 1);
                sm[row * HC_STRIDE + col] = c_[mi][nj][q];
            }
    __syncthreads();

    int ty = tid >> 4, tx = tid & 15;
    int jt_g = ct * 16 + tx;
    int t = jt_g >> 3;
    float cf_i[8];
    #pragma unroll
    for (int i = 0; i < 8; ++i)
        cf_i[i] = g_cf[(b * N_ + m0 + ty * 8 + i) * T_ + t];

    int ch2 = ct >> 1;
    int n8g = (ct & 1) * 16 + tx;
    int u   = mt * 8 + (ty >> 1);
    int sel = ty & 1;
    size_t base_idx = ((size_t)((b * 2 + ch2) * 64 + u) * 32 + n8g) * 32;
    char* hb = (char*)g_Hth;

    #pragma unroll
    for (int jj = 0; jj < 8; ++jj) {
        float v[8];
        #pragma unroll
        for (int i = 0; i < 8; ++i)
            v[i] = sm[(ty * 8 + i) * HC_STRIDE + tx * 8 + jj] * cf_i[i];
        #pragma unroll
        for (int ip = 0; ip < 4; ++ip) {
            uint32_t hv = h2pack(v[2 * ip], v[2 * ip + 1]);
            size_t idx = base_idx + jj * 4 + ip;
            *(uint32_t*)(hb + idx * 8 + sel * 4) = hv;
        }
    }
}

// ---------------- K2: cp.async fp16 HMMA GEMM, k-chunk 64, 2 CTA/SM ------------
#define RST 68
__global__ __launch_bounds__(128, 2) void k_main() {
    extern __shared__ float sm[];
    uint32_t sbase = smem_u32(sm);

    int bx = blockIdx.x;
    if (bx == 0 && threadIdx.x == 0) g_ctr = 0;   // reset barrier for k_post
    int b  = bx >> 5;
    int nt = (bx >> 2) & 7;
    int ch = bx & 3;
    int ch2 = ch >> 1, chH = ch & 1;
    int n0 = nt * 128;
    int tid = threadIdx.x;
    int wid = tid >> 5, lane = tid & 31;
    int mw = wid & 1, nw = wid >> 1;
    int skew = (bx & 1) * 8;          // desync co-resident CTA pair L2 streams

    const char* EA = (const char*)(g_E4h + (size_t)(b * 8 + nt) * 64 * 256);
    const char* HB = (const char*)(g_Hth + (size_t)(b * 2 + ch2) * 64 * 1024) + chH * 4096;
    uint32_t sA = sbase;              // 3 x 16384 B
    uint32_t sB = sbase + 49152;      // 3 x 16384 B

    auto issue = [&](int s) {         // s = logical chunk; data chunk is skewed
        int buf = s % 3;
        int u0 = ((s + skew) & 15) * 4;
        #pragma unroll
        for (int p = 0; p < 8; ++p) {
            int idx = p * 128 + tid;
            int ul = idx >> 8, rem = (idx & 255) * 16;
            cp16(sA + buf * 16384 + idx * 16, EA + (size_t)(u0 + ul) * 4096 + rem);
            cp16(sB + buf * 16384 + idx * 16, HB + (size_t)(u0 + ul) * 8192 + rem);
        }
        CP_COMMIT();
    };

    issue(0); issue(1);

    float c_[4][8][4];
    #pragma unroll
    for (int i = 0; i < 4; ++i)
        #pragma unroll
        for (int j = 0; j < 8; ++j)
            #pragma unroll
            for (int q = 0; q < 4; ++q) c_[i][j][q] = 0.0f;

    for (int kc = 0; kc < 16; ++kc) {
        if (kc < 14) { CP_WAIT(1); } else { CP_WAIT(0); }
        __syncthreads();

        int buf = kc % 3;
        const uint4* Au = (const uint4*)(sm) + buf * 1024;
        const uint2* Bu = (const uint2*)(sm + 12288) + buf * 2048;

        #pragma unroll
        for (int ul = 0; ul < 4; ++ul) {
            uint4 a[4];
            #pragma unroll
            for (int mi = 0; mi < 4; ++mi)
                a[mi] = Au[(ul * 8 + mw * 4 + mi) * 32 + lane];
            uint2 bv[8];
            #pragma unroll
            for (int nj = 0; nj < 8; ++nj)
                bv[nj] = Bu[(ul * 16 + nw * 8 + nj) * 32 + lane];
            #pragma unroll
            for (int mi = 0; mi < 4; ++mi)
                #pragma unroll
                for (int nj = 0; nj < 8; ++nj)
                    mma16816(c_[mi][nj], a[mi], bv[nj]);
        }

        if (kc < 14) issue(kc + 2);
    }

    // ---- epilogue: scale by u_t, reduce the CTA's two t's in smem, write plane
    __syncthreads();
    int t = ch * 2 + nw;
    float* red = sm + mw * 64 * RST;

    if (nw == 0) {
        #pragma unroll
        for (int mi = 0; mi < 4; ++mi) {
            #pragma unroll
            for (int ro = 0; ro < 2; ++ro) {
                int rloc = mi * 16 + (lane >> 2) + ro * 8;
                float u = g_u[(b * N_ + n0 + mw * 64 + rloc) * T_ + t];
                #pragma unroll
                for (int nj = 0; nj < 8; ++nj) {
                    float2 v;
                    v.x = c_[mi][nj][ro * 2 + 0] * u;
                    v.y = c_[mi][nj][ro * 2 + 1] * u;
                    *(float2*)(red + rloc * RST + nj * 8 + (lane & 3) * 2) = v;
                }
            }
        }
    }
    __syncthreads();
    if (nw == 1) {
        #pragma unroll
        for (int mi = 0; mi < 4; ++mi) {
            #pragma unroll
            for (int ro = 0; ro < 2; ++ro) {
                int rloc = mi * 16 + (lane >> 2) + ro * 8;
                int n = n0 + mw * 64 + rloc;
                float u = g_u[(b * N_ + n) * T_ + t];
                float* dst = g_preP[ch] + (size_t)(b * N_ + n) * CO + (lane & 3) * 2;
                #pragma unroll
                for (int nj = 0; nj < 8; ++nj) {
                    float2 p = *(const float2*)(red + rloc * RST + nj * 8 + (lane & 3) * 2);
                    float2 v;
                    v.x = fmaf(c_[mi][nj][ro * 2 + 0], u, p.x);
                    v.y = fmaf(c_[mi][nj][ro * 2 + 1], u, p.y);
                    *(float2*)(dst + nj * 8) = v;
                }
            }
        }
    }
}

// ---------------- K3: fused plane-sum + BN stats + device barrier + apply ------
// grid 128 x 256 thr, 64 rows per block. All blocks resident -> spin is safe.
__global__ __launch_bounds__(256) void k_post(float* __restrict__ out,
                                              const float* __restrict__ gamma,
                                              const float* __restrict__ beta) {
    __shared__ float sh[256], sh2[256];
    __shared__ float sscale[64], sbias[64];
    int blk = blockIdx.x;
    int tid = threadIdx.x;
    int o = tid & 63, rg = tid >> 6;
    int r0 = blk * 64;

    // phase 1: sum 4 partial planes -> g_pre, accumulate block stats
    float s = 0.0f, s2 = 0.0f;
    for (int r = r0 + rg; r < r0 + 64; r += 4) {
        float p = g_preP[0][r * CO + o] + g_preP[1][r * CO + o]
                + g_preP[2][r * CO + o] + g_preP[3][r * CO + o];
        g_pre[r * CO + o] = p;
        s += p; s2 += p * p;
    }
    sh[tid] = s; sh2[tid] = s2;
    __syncthreads();
    if (rg == 0) {
        g_part [blk * 64 + o] = s  + sh [o + 64] + sh [o + 128] + sh [o + 192];
        g_part2[blk * 64 + o] = s2 + sh2[o + 64] + sh2[o + 128] + sh2[o + 192];
    }
    __syncthreads();

    // device-wide barrier (all 128 blocks resident)
    if (tid == 0) {
        __threadfence();
        atomicAdd(&g_ctr, 1);
        while (atomicAdd(&g_ctr, 0) < 128) { __nanosleep(64); }
    }
    __syncthreads();

    // phase 2: reduce all partials (L2 reads), compute scale/bias
    float ps = 0.0f, ps2 = 0.0f;
    for (int i = rg; i < 128; i += 4) {
        ps  += __ldcg(&g_part [i * 64 + o]);
        ps2 += __ldcg(&g_part2[i * 64 + o]);
    }
    sh[tid] = ps; sh2[tid] = ps2;
    __syncthreads();
    if (tid < 64) {
        float ts  = sh [o] + sh [o + 64] + sh [o + 128] + sh [o + 192];
        float ts2 = sh2[o] + sh2[o + 64] + sh2[o + 128] + sh2[o + 192];
        float inv = 1.0f / (float)NB;
        float mean = ts * inv;
        float var = ts2 * inv - mean * mean;
        float sc = gamma[o] * rsqrtf(var + 1e-5f);
        sscale[o] = sc;
        sbias[o]  = beta[o] - mean * sc;
    }
    __syncthreads();

    // phase 3: apply BN + ReLU for this block's 64 rows
    #pragma unroll
    for (int q = 0; q < 4; ++q) {
        int e0 = blk * 4096 + (q * 256 + tid) * 4;
        int o0 = e0 & 63;
        float4 p = *(const float4*)(g_pre + e0);
        float4 r;
        r.x = fmaxf(fmaf(p.x, sscale[o0 + 0], sbias[o0 + 0]), 0.0f);
        r.y = fmaxf(fmaf(p.y, sscale[o0 + 1], sbias[o0 + 1]), 0.0f);
        r.z = fmaxf(fmaf(p.z, sscale[o0 + 2], sbias[o0 + 2]), 0.0f);
        r.w = fmaxf(fmaf(p.w, sscale[o0 + 3], sbias[o0 + 3]), 0.0f);
        *(float4*)(out + e0) = r;
    }
}

// ---------------- launch ----------------
extern "C" void kernel_launch(void* const* d_in, const int* in_sizes, int n_in,
                              void* d_out, int out_size) {
    (void)in_sizes; (void)n_in; (void)out_size;
    const float* pts   = (const float*)d_in[0];
    const float* trans = (const float*)d_in[1];
    const float* func  = (const float*)d_in[2];
    const float* kt    = (const float*)d_in[3];
    const float* gamma = (const float*)d_in[4];
    const float* beta  = (const float*)d_in[5];
    float* out = (float*)d_out;

    cudaFuncSetAttribute(k_main, cudaFuncAttributeMaxDynamicSharedMemorySize, 98304);
    cudaFuncSetAttribute(k_H,    cudaFuncAttributeMaxDynamicSharedMemorySize, 69632);

    k_prepE<<<128, 512>>>(pts, trans, kt);
    k_H<<<256, 256, 69632>>>(func);
    k_main<<<256, 128, 98304>>>();
    k_post<<<128, 256>>>(out, gamma, beta);
}